// round 6
// baseline (speedup 1.0000x reference)
#include <cuda_runtime.h>
#include <cuda_bf16.h>
#include <cstdint>
#include <math.h>

#define HT   128
#define CC   256
#define FF   128
#define BB   4
#define NU   32
#define NOUT 2304
#define NG   1024
#define PIF  3.14159265358979323846f

typedef __nv_bfloat16 bf16;

// ---------------- scratch globals ----------------
__device__ __align__(16) bf16  g_Wgh[4 * NG * 32];
__device__ __align__(16) bf16  g_Wgl[4 * NG * 32];
__device__ __align__(16) float g_bg[4 * NG];
__device__ __align__(16) float g_Hc[128 * 32];
__device__ __align__(16) float g_Wc[128 * 32];
__device__ __align__(16) float g_Cc[32];
__device__ __align__(16) bf16  g_x4h[(size_t)16384 * 32];
__device__ __align__(16) bf16  g_x4l[(size_t)16384 * 32];
__device__ __align__(16) bf16  g_WpTh[(size_t)FF * CC];
__device__ __align__(16) bf16  g_WpTl[(size_t)FF * CC];
__device__ __align__(16) float g_ker2[(size_t)16384 * NG];   // [p'][g*256+c]

__device__ __forceinline__ void split_bf(float v, bf16& hi, bf16& lo) {
    hi = __float2bfloat16(v);
    lo = __float2bfloat16(v - __bfloat162float(hi));
}
__device__ __forceinline__ void mma16816(float c[4], const uint32_t a[4], const uint32_t b[2]) {
    asm volatile(
        "mma.sync.aligned.m16n8k16.row.col.f32.bf16.bf16.f32 "
        "{%0,%1,%2,%3}, {%4,%5,%6,%7}, {%8,%9}, {%0,%1,%2,%3};"
        : "+f"(c[0]), "+f"(c[1]), "+f"(c[2]), "+f"(c[3])
        : "r"(a[0]), "r"(a[1]), "r"(a[2]), "r"(a[3]), "r"(b[0]), "r"(b[1]));
}
__device__ __forceinline__ int grp(int t, int par) { return (t == 0) ? 0 : (t == 2) ? 1 : (par ? 0 : 1); }

// ---------------------------------------------------------------------------
// prep
// ---------------------------------------------------------------------------
__global__ __launch_bounds__(256) void prep_kernel(
    const float* __restrict__ Wo, const float* __restrict__ bo,
    const float* __restrict__ Wp,
    const float* __restrict__ W1, const float* __restrict__ b1)
{
    int idx = blockIdx.x * 256 + threadIdx.x;
    if (idx < 4 * NG * 32) {
        int par = idx >> 15, rem = idx & 32767;
        int n = rem >> 5, k = rem & 31;
        int g = n >> 8, c = n & 255, gr = g >> 1, gc = g & 1;
        int ph = par >> 1, pw = par & 1;
        float s = 0.0f;
        #pragma unroll
        for (int tr = 0; tr < 3; ++tr)
            #pragma unroll
            for (int tc = 0; tc < 3; ++tc)
                if (grp(tr, ph) == gr && grp(tc, pw) == gc)
                    s += Wo[(size_t)k * NOUT + (tr * 3 + tc) * 256 + c];
        bf16 hi, lo; split_bf(s, hi, lo);
        g_Wgh[idx] = hi; g_Wgl[idx] = lo;
    } else if ((idx -= 4 * NG * 32) < 4 * NG) {
        int par = idx >> 10, n = idx & 1023;
        int g = n >> 8, c = n & 255, gr = g >> 1, gc = g & 1;
        int ph = par >> 1, pw = par & 1;
        float s = 0.0f;
        #pragma unroll
        for (int tr = 0; tr < 3; ++tr)
            #pragma unroll
            for (int tc = 0; tc < 3; ++tc)
                if (grp(tr, ph) == gr && grp(tc, pw) == gc)
                    s += bo[(tr * 3 + tc) * 256 + c];
        g_bg[idx] = s;
    } else if ((idx -= 4 * NG) < FF * CC) {
        int n = idx >> 8, k = idx & 255;
        bf16 hi, lo; split_bf(Wp[(size_t)k * FF + n], hi, lo);
        g_WpTh[idx] = hi; g_WpTl[idx] = lo;
    } else if ((idx -= FF * CC) < 4096) {
        int h = idx >> 5, j = idx & 31;
        float s = 0.0f;
        for (int i = 0; i < 25; ++i) {
            float f = 1.0f + (float)i * (1.0f / 24.0f);
            s += cosf(PIF * (2.0f * h * (1.0f / 127.0f) + 1.0f) * f) * W1[i * 32 + j];
        }
        g_Hc[idx] = s;
    } else if ((idx -= 4096) < 4096) {
        int w = idx >> 5, j = idx & 31;
        float s = 0.0f;
        for (int i = 0; i < 25; ++i) {
            float f = 1.0f + (float)i * (1.0f / 24.0f);
            s += cosf(PIF * (2.0f * w * (1.0f / 127.0f) + 1.0f) * f) * W1[(25 + i) * 32 + j];
        }
        g_Wc[idx] = s;
    } else if ((idx -= 4096) < 32) {
        int j = idx;
        float s = b1[j];
        for (int i = 0; i < 50; ++i) {
            float f = 1.0f + (float)(i % 25) * (1.0f / 24.0f);
            s += cosf(PIF * 5.0f * f) * W1[(50 + i) * 32 + j];
        }
        for (int i = 100; i < 118; ++i) s -= W1[i * 32 + j];
        g_Cc[j] = s;
    }
}

// ---------------------------------------------------------------------------
// mlp -> x4 hi/lo, parity-major p'
// ---------------------------------------------------------------------------
__global__ __launch_bounds__(256) void mlp_kernel(
    const float* __restrict__ W2, const float* __restrict__ b2,
    const float* __restrict__ W3, const float* __restrict__ b3,
    const float* __restrict__ W4, const float* __restrict__ b4)
{
    __shared__ float xa[16][32];
    __shared__ float xb[16][32];
    const int tid = threadIdx.x;
    const int pix0 = blockIdx.x * 16;

    for (int o = tid; o < 512; o += 256) {
        int p = o >> 5, j = o & 31;
        int pix = pix0 + p, h = pix >> 7, w = pix & 127;
        xa[p][j] = fmaxf(g_Hc[h * 32 + j] + g_Wc[w * 32 + j] + g_Cc[j], 0.0f);
    }
    __syncthreads();
    for (int o = tid; o < 512; o += 256) {
        int p = o >> 5, j = o & 31;
        float s = b2[j];
        #pragma unroll
        for (int k = 0; k < NU; ++k) s += xa[p][k] * W2[k * NU + j];
        xb[p][j] = fmaxf(s, 0.0f);
    }
    __syncthreads();
    for (int o = tid; o < 512; o += 256) {
        int p = o >> 5, j = o & 31;
        float s = b3[j];
        #pragma unroll
        for (int k = 0; k < NU; ++k) s += xb[p][k] * W3[k * NU + j];
        xa[p][j] = fmaxf(s, 0.0f);
    }
    __syncthreads();
    for (int o = tid; o < 512; o += 256) {
        int p = o >> 5, j = o & 31;
        float s = b4[j];
        #pragma unroll
        for (int k = 0; k < NU; ++k) s += xa[p][k] * W4[k * NU + j];
        float v = fmaxf(s, 0.0f);
        int pix = pix0 + p, h = pix >> 7, w = pix & 127;
        int pp = (((h & 1) << 1) | (w & 1)) * 4096 + (h >> 1) * 64 + (w >> 1);
        bf16 hi, lo; split_bf(v, hi, lo);
        size_t o2 = (size_t)pp * 32 + j;
        g_x4h[o2] = hi; g_x4l[o2] = lo;
    }
}

// ---------------------------------------------------------------------------
// gemm1: g_ker2 = x4 @ Wg[par] + bg[par]
// ---------------------------------------------------------------------------
__global__ __launch_bounds__(256) void gemm1_kernel()
{
    __shared__ __align__(16) bf16 As[128 * 72];
    __shared__ __align__(16) bf16 Bs[128 * 72];

    const int tid = threadIdx.x;
    const int wid = tid >> 5, lane = tid & 31;
    const int gid = lane >> 2, tig = lane & 3;
    const int m0 = blockIdx.x * 128, n0g = blockIdx.y * 128;
    const int par = blockIdx.x >> 5;
    const int wm0 = (wid & 3) * 32, wn0 = (wid >> 2) * 64;

    const bf16* WgH = g_Wgh + (size_t)par * NG * 32;
    const bf16* WgL = g_Wgl + (size_t)par * NG * 32;

    for (int i = tid; i < 512; i += 256) {
        int r = i >> 2, q = (i & 3) * 8;
        *(uint4*)&As[r * 72 + q]      = *(const uint4*)&g_x4h[(size_t)(m0 + r) * 32 + q];
        *(uint4*)&As[r * 72 + 32 + q] = *(const uint4*)&g_x4l[(size_t)(m0 + r) * 32 + q];
        *(uint4*)&Bs[r * 72 + q]      = *(const uint4*)&WgH[(size_t)(n0g + r) * 32 + q];
        *(uint4*)&Bs[r * 72 + 32 + q] = *(const uint4*)&WgL[(size_t)(n0g + r) * 32 + q];
    }
    __syncthreads();

    float c[2][8][4];
    #pragma unroll
    for (int i = 0; i < 2; ++i)
        #pragma unroll
        for (int j = 0; j < 8; ++j)
            #pragma unroll
            for (int e = 0; e < 4; ++e) c[i][j][e] = 0.0f;

    #pragma unroll
    for (int combo = 0; combo < 3; ++combo) {
        const int aoff = (combo == 2) ? 32 : 0;
        const int boff = (combo == 1) ? 32 : 0;
        #pragma unroll
        for (int ks = 0; ks < 2; ++ks) {
            const int kb = ks * 16;
            uint32_t a[2][4];
            #pragma unroll
            for (int mf = 0; mf < 2; ++mf) {
                int row = wm0 + mf * 16 + gid;
                a[mf][0] = *(const uint32_t*)&As[row * 72       + aoff + kb + tig * 2];
                a[mf][1] = *(const uint32_t*)&As[(row + 8) * 72 + aoff + kb + tig * 2];
                a[mf][2] = *(const uint32_t*)&As[row * 72       + aoff + kb + tig * 2 + 8];
                a[mf][3] = *(const uint32_t*)&As[(row + 8) * 72 + aoff + kb + tig * 2 + 8];
            }
            uint32_t b[8][2];
            #pragma unroll
            for (int nf = 0; nf < 8; ++nf) {
                int n = wn0 + nf * 8 + gid;
                b[nf][0] = *(const uint32_t*)&Bs[n * 72 + boff + kb + tig * 2];
                b[nf][1] = *(const uint32_t*)&Bs[n * 72 + boff + kb + tig * 2 + 8];
            }
            #pragma unroll
            for (int mf = 0; mf < 2; ++mf)
                #pragma unroll
                for (int nf = 0; nf < 8; ++nf)
                    mma16816(c[mf][nf], a[mf], b[nf]);
        }
    }

    const float* bgp = g_bg + par * NG;
    #pragma unroll
    for (int mf = 0; mf < 2; ++mf) {
        int gm = m0 + wm0 + mf * 16 + gid;
        #pragma unroll
        for (int nf = 0; nf < 8; ++nf) {
            int gn = n0g + wn0 + nf * 8 + tig * 2;
            float bx = __ldg(&bgp[gn]), by = __ldg(&bgp[gn + 1]);
            float2 v0 = { c[mf][nf][0] + bx, c[mf][nf][1] + by };
            float2 v1 = { c[mf][nf][2] + bx, c[mf][nf][3] + by };
            *(float2*)&g_ker2[(size_t)gm * NG + gn]       = v0;
            *(float2*)&g_ker2[(size_t)(gm + 8) * NG + gn] = v1;
        }
    }
}

// ---------------------------------------------------------------------------
// fused gemm2: out[m,128] = conv(main_in, ker2) @ Wp + bp
// grid 512: blockIdx.x = h*4 + b (same-h CTAs adjacent => ker2 L2 reuse)
// CTA = one (b,h) row: 128 m-rows, K=256 in 8 chunks of 32 channels.
// A-tile built in-place: y = sum_g ker2_g * src_g (fp32), split to bf16 hi/lo.
// ---------------------------------------------------------------------------
__global__ __launch_bounds__(256) void gemm2_fused_kernel(
    const float* __restrict__ main_in,
    const float* __restrict__ bp, float* __restrict__ out)
{
    __shared__ __align__(16) bf16  As[128 * 72];
    __shared__ __align__(16) bf16  Bs[128 * 72];
    __shared__ __align__(16) float Xs[2 * 64 * 20];   // [r][col][16ch + pad4]

    const int tid = threadIdx.x;
    const int wid = tid >> 5, lane = tid & 31;
    const int gid = lane >> 2, tig = lane & 3;
    const int h = blockIdx.x >> 2, b = blockIdx.x & 3;
    const int m0 = b * 16384 + h * 128;
    const int wm0 = (wid & 3) * 32, wn0 = (wid >> 2) * 64;

    const int rA = (h - 1) >> 1, rB = (h + 1) >> 1;
    const bool vrA = h >= 1, vrB = h <= 126;

    // per-thread A-build identity
    const int aw   = tid >> 1;                 // w = 0..127
    const int coff = (tid & 1) * 8;            // channel offset within 16-ch sub
    const int par  = ((h & 1) << 1) | (aw & 1);
    const size_t pbase = ((size_t)par * 4096 + (h >> 1) * 64 + (aw >> 1)) * NG;
    const int cAq = (aw - 1) >> 1, cBq = (aw + 1) >> 1;
    const bool vcA = aw >= 1, vcB = aw <= 126;

    float c[2][8][4];
    #pragma unroll
    for (int i = 0; i < 2; ++i)
        #pragma unroll
        for (int j = 0; j < 8; ++j)
            #pragma unroll
            for (int e = 0; e < 4; ++e) c[i][j][e] = 0.0f;

    for (int chunk = 0; chunk < 8; ++chunk) {
        const int kc = chunk * 32;

        #pragma unroll
        for (int sub = 0; sub < 2; ++sub) {
            const int c0 = kc + sub * 16;
            __syncthreads();   // prev MMA / prev Xs readers done
            // stage Xs: 2 rows x 64 cols x 16 ch
            #pragma unroll
            for (int q = 0; q < 2; ++q) {
                int idx = tid * 2 + q;              // 0..511
                int r   = idx >> 8;
                int col = (idx >> 2) & 63;
                int qq  = idx & 3;
                float4 v = make_float4(0.f, 0.f, 0.f, 0.f);
                int  srow = r ? rB : rA;
                bool vr   = r ? vrB : vrA;
                if (vr)
                    v = *(const float4*)&main_in[(((size_t)b * 64 + srow) * 64 + col) * CC + c0 + qq * 4];
                *(float4*)&Xs[(r * 64 + col) * 20 + qq * 4] = v;
            }
            __syncthreads();
            // build 8 channels of As for row aw
            {
                const float* kbp = g_ker2 + pbase + c0 + coff;
                float ks[4][8], ss[4][8];
                #pragma unroll
                for (int g = 0; g < 4; ++g) {
                    *(float4*)&ks[g][0] = *(const float4*)&kbp[g * 256];
                    *(float4*)&ks[g][4] = *(const float4*)&kbp[g * 256 + 4];
                }
                #pragma unroll
                for (int g = 0; g < 4; ++g) {
                    int  rr  = g >> 1;
                    int  col = (g & 1) ? cBq : cAq;
                    bool ok  = (g & 1) ? vcB : vcA;
                    float4 va = make_float4(0.f, 0.f, 0.f, 0.f), vb = va;
                    if (ok) {
                        va = *(const float4*)&Xs[(rr * 64 + col) * 20 + coff];
                        vb = *(const float4*)&Xs[(rr * 64 + col) * 20 + coff + 4];
                    }
                    *(float4*)&ss[g][0] = va;
                    *(float4*)&ss[g][4] = vb;
                }
                uint32_t hu[4], lu[4];
                #pragma unroll
                for (int j2 = 0; j2 < 4; ++j2) {
                    bf16 h0, l0, h1, l1;
                    float y0 = ks[0][j2*2]   * ss[0][j2*2]   + ks[1][j2*2]   * ss[1][j2*2]
                             + ks[2][j2*2]   * ss[2][j2*2]   + ks[3][j2*2]   * ss[3][j2*2];
                    float y1 = ks[0][j2*2+1] * ss[0][j2*2+1] + ks[1][j2*2+1] * ss[1][j2*2+1]
                             + ks[2][j2*2+1] * ss[2][j2*2+1] + ks[3][j2*2+1] * ss[3][j2*2+1];
                    split_bf(y0, h0, l0);
                    split_bf(y1, h1, l1);
                    hu[j2] = (uint32_t)__bfloat16_as_ushort(h0) | ((uint32_t)__bfloat16_as_ushort(h1) << 16);
                    lu[j2] = (uint32_t)__bfloat16_as_ushort(l0) | ((uint32_t)__bfloat16_as_ushort(l1) << 16);
                }
                const int cc = sub * 16 + coff;
                *(uint4*)&As[aw * 72 + cc]      = make_uint4(hu[0], hu[1], hu[2], hu[3]);
                *(uint4*)&As[aw * 72 + 32 + cc] = make_uint4(lu[0], lu[1], lu[2], lu[3]);
            }
        }

        // B tile for this chunk
        for (int i = tid; i < 512; i += 256) {
            int r = i >> 2, q = (i & 3) * 8;
            *(uint4*)&Bs[r * 72 + q]      = *(const uint4*)&g_WpTh[(size_t)r * CC + kc + q];
            *(uint4*)&Bs[r * 72 + 32 + q] = *(const uint4*)&g_WpTl[(size_t)r * CC + kc + q];
        }
        __syncthreads();

        #pragma unroll
        for (int combo = 0; combo < 3; ++combo) {
            const int aoff = (combo == 2) ? 32 : 0;
            const int boff = (combo == 1) ? 32 : 0;
            #pragma unroll
            for (int ks2 = 0; ks2 < 2; ++ks2) {
                const int kb = ks2 * 16;
                uint32_t a[2][4];
                #pragma unroll
                for (int mf = 0; mf < 2; ++mf) {
                    int row = wm0 + mf * 16 + gid;
                    a[mf][0] = *(const uint32_t*)&As[row * 72       + aoff + kb + tig * 2];
                    a[mf][1] = *(const uint32_t*)&As[(row + 8) * 72 + aoff + kb + tig * 2];
                    a[mf][2] = *(const uint32_t*)&As[row * 72       + aoff + kb + tig * 2 + 8];
                    a[mf][3] = *(const uint32_t*)&As[(row + 8) * 72 + aoff + kb + tig * 2 + 8];
                }
                uint32_t bfr[8][2];
                #pragma unroll
                for (int nf = 0; nf < 8; ++nf) {
                    int n = wn0 + nf * 8 + gid;
                    bfr[nf][0] = *(const uint32_t*)&Bs[n * 72 + boff + kb + tig * 2];
                    bfr[nf][1] = *(const uint32_t*)&Bs[n * 72 + boff + kb + tig * 2 + 8];
                }
                #pragma unroll
                for (int mf = 0; mf < 2; ++mf)
                    #pragma unroll
                    for (int nf = 0; nf < 8; ++nf)
                        mma16816(c[mf][nf], a[mf], bfr[nf]);
            }
        }
    }

    #pragma unroll
    for (int mf = 0; mf < 2; ++mf) {
        int gm = m0 + wm0 + mf * 16 + gid;
        #pragma unroll
        for (int nf = 0; nf < 8; ++nf) {
            int gn = wn0 + nf * 8 + tig * 2;
            float bx = __ldg(&bp[gn]), by = __ldg(&bp[gn + 1]);
            float2 v0 = { c[mf][nf][0] + bx, c[mf][nf][1] + by };
            float2 v1 = { c[mf][nf][2] + bx, c[mf][nf][3] + by };
            *(float2*)&out[(size_t)gm * FF + gn]       = v0;
            *(float2*)&out[(size_t)(gm + 8) * FF + gn] = v1;
        }
    }
}

// ---------------------------------------------------------------------------
extern "C" void kernel_launch(void* const* d_in, const int* in_sizes, int n_in,
                              void* d_out, int out_size)
{
    const float* main_in = (const float*)d_in[0];
    const float* W1 = (const float*)d_in[2];
    const float* b1 = (const float*)d_in[3];
    const float* W2 = (const float*)d_in[4];
    const float* b2 = (const float*)d_in[5];
    const float* W3 = (const float*)d_in[6];
    const float* b3 = (const float*)d_in[7];
    const float* W4 = (const float*)d_in[8];
    const float* b4 = (const float*)d_in[9];
    const float* Wo = (const float*)d_in[10];
    const float* bo = (const float*)d_in[11];
    const float* Wp = (const float*)d_in[12];
    const float* bp = (const float*)d_in[13];
    float* out = (float*)d_out;

    const int prep_elems = 4 * NG * 32 + 4 * NG + FF * CC + 4096 + 4096 + 32;
    prep_kernel<<<(prep_elems + 255) / 256, 256>>>(Wo, bo, Wp, W1, b1);
    mlp_kernel<<<1024, 256>>>(W2, b2, W3, b3, W4, b4);
    gemm1_kernel<<<dim3(128, 8), 256>>>();
    gemm2_fused_kernel<<<512, 256>>>(main_in, bp, out);
}

// round 7
// speedup vs baseline: 1.0223x; 1.0223x over previous
#include <cuda_runtime.h>
#include <cuda_bf16.h>
#include <cstdint>
#include <math.h>

#define HT   128
#define CC   256
#define FF   128
#define BB   4
#define NU   32
#define NOUT 2304
#define NG   1024
#define PIF  3.14159265358979323846f

typedef __nv_bfloat16 bf16;

// ---------------- scratch globals ----------------
__device__ __align__(16) bf16  g_Wgh[4 * NG * 32];
__device__ __align__(16) bf16  g_Wgl[4 * NG * 32];
__device__ __align__(16) float g_bg[4 * NG];
__device__ __align__(16) float g_Hc[128 * 32];
__device__ __align__(16) float g_Wc[128 * 32];
__device__ __align__(16) float g_Cc[32];
__device__ __align__(16) bf16  g_x4h[(size_t)16384 * 32];
__device__ __align__(16) bf16  g_x4l[(size_t)16384 * 32];
__device__ __align__(16) bf16  g_WpTh[(size_t)FF * CC];
__device__ __align__(16) bf16  g_WpTl[(size_t)FF * CC];
__device__ __align__(16) float g_ker2[(size_t)16384 * NG];   // [p'][g*256+c]

__device__ __forceinline__ void split_bf(float v, bf16& hi, bf16& lo) {
    hi = __float2bfloat16(v);
    lo = __float2bfloat16(v - __bfloat162float(hi));
}
__device__ __forceinline__ void mma16816(float c[4], const uint32_t a[4], const uint32_t b[2]) {
    asm volatile(
        "mma.sync.aligned.m16n8k16.row.col.f32.bf16.bf16.f32 "
        "{%0,%1,%2,%3}, {%4,%5,%6,%7}, {%8,%9}, {%0,%1,%2,%3};"
        : "+f"(c[0]), "+f"(c[1]), "+f"(c[2]), "+f"(c[3])
        : "r"(a[0]), "r"(a[1]), "r"(a[2]), "r"(a[3]), "r"(b[0]), "r"(b[1]));
}
__device__ __forceinline__ int grp(int t, int par) { return (t == 0) ? 0 : (t == 2) ? 1 : (par ? 0 : 1); }

// ---------------------------------------------------------------------------
// prep
// ---------------------------------------------------------------------------
__global__ __launch_bounds__(256) void prep_kernel(
    const float* __restrict__ Wo, const float* __restrict__ bo,
    const float* __restrict__ Wp,
    const float* __restrict__ W1, const float* __restrict__ b1)
{
    int idx = blockIdx.x * 256 + threadIdx.x;
    if (idx < 4 * NG * 32) {
        int par = idx >> 15, rem = idx & 32767;
        int n = rem >> 5, k = rem & 31;
        int g = n >> 8, c = n & 255, gr = g >> 1, gc = g & 1;
        int ph = par >> 1, pw = par & 1;
        float s = 0.0f;
        #pragma unroll
        for (int tr = 0; tr < 3; ++tr)
            #pragma unroll
            for (int tc = 0; tc < 3; ++tc)
                if (grp(tr, ph) == gr && grp(tc, pw) == gc)
                    s += Wo[(size_t)k * NOUT + (tr * 3 + tc) * 256 + c];
        bf16 hi, lo; split_bf(s, hi, lo);
        g_Wgh[idx] = hi; g_Wgl[idx] = lo;
    } else if ((idx -= 4 * NG * 32) < 4 * NG) {
        int par = idx >> 10, n = idx & 1023;
        int g = n >> 8, c = n & 255, gr = g >> 1, gc = g & 1;
        int ph = par >> 1, pw = par & 1;
        float s = 0.0f;
        #pragma unroll
        for (int tr = 0; tr < 3; ++tr)
            #pragma unroll
            for (int tc = 0; tc < 3; ++tc)
                if (grp(tr, ph) == gr && grp(tc, pw) == gc)
                    s += bo[(tr * 3 + tc) * 256 + c];
        g_bg[idx] = s;
    } else if ((idx -= 4 * NG) < FF * CC) {
        int n = idx >> 8, k = idx & 255;
        bf16 hi, lo; split_bf(Wp[(size_t)k * FF + n], hi, lo);
        g_WpTh[idx] = hi; g_WpTl[idx] = lo;
    } else if ((idx -= FF * CC) < 4096) {
        int h = idx >> 5, j = idx & 31;
        float s = 0.0f;
        for (int i = 0; i < 25; ++i) {
            float f = 1.0f + (float)i * (1.0f / 24.0f);
            s += cosf(PIF * (2.0f * h * (1.0f / 127.0f) + 1.0f) * f) * W1[i * 32 + j];
        }
        g_Hc[idx] = s;
    } else if ((idx -= 4096) < 4096) {
        int w = idx >> 5, j = idx & 31;
        float s = 0.0f;
        for (int i = 0; i < 25; ++i) {
            float f = 1.0f + (float)i * (1.0f / 24.0f);
            s += cosf(PIF * (2.0f * w * (1.0f / 127.0f) + 1.0f) * f) * W1[(25 + i) * 32 + j];
        }
        g_Wc[idx] = s;
    } else if ((idx -= 4096) < 32) {
        int j = idx;
        float s = b1[j];
        for (int i = 0; i < 50; ++i) {
            float f = 1.0f + (float)(i % 25) * (1.0f / 24.0f);
            s += cosf(PIF * 5.0f * f) * W1[(50 + i) * 32 + j];
        }
        for (int i = 100; i < 118; ++i) s -= W1[i * 32 + j];
        g_Cc[j] = s;
    }
}

// ---------------------------------------------------------------------------
// mlp -> x4 hi/lo, parity-major p'
// ---------------------------------------------------------------------------
__global__ __launch_bounds__(256) void mlp_kernel(
    const float* __restrict__ W2, const float* __restrict__ b2,
    const float* __restrict__ W3, const float* __restrict__ b3,
    const float* __restrict__ W4, const float* __restrict__ b4)
{
    __shared__ float xa[16][32];
    __shared__ float xb[16][32];
    const int tid = threadIdx.x;
    const int pix0 = blockIdx.x * 16;

    for (int o = tid; o < 512; o += 256) {
        int p = o >> 5, j = o & 31;
        int pix = pix0 + p, h = pix >> 7, w = pix & 127;
        xa[p][j] = fmaxf(g_Hc[h * 32 + j] + g_Wc[w * 32 + j] + g_Cc[j], 0.0f);
    }
    __syncthreads();
    for (int o = tid; o < 512; o += 256) {
        int p = o >> 5, j = o & 31;
        float s = b2[j];
        #pragma unroll
        for (int k = 0; k < NU; ++k) s += xa[p][k] * W2[k * NU + j];
        xb[p][j] = fmaxf(s, 0.0f);
    }
    __syncthreads();
    for (int o = tid; o < 512; o += 256) {
        int p = o >> 5, j = o & 31;
        float s = b3[j];
        #pragma unroll
        for (int k = 0; k < NU; ++k) s += xb[p][k] * W3[k * NU + j];
        xa[p][j] = fmaxf(s, 0.0f);
    }
    __syncthreads();
    for (int o = tid; o < 512; o += 256) {
        int p = o >> 5, j = o & 31;
        float s = b4[j];
        #pragma unroll
        for (int k = 0; k < NU; ++k) s += xa[p][k] * W4[k * NU + j];
        float v = fmaxf(s, 0.0f);
        int pix = pix0 + p, h = pix >> 7, w = pix & 127;
        int pp = (((h & 1) << 1) | (w & 1)) * 4096 + (h >> 1) * 64 + (w >> 1);
        bf16 hi, lo; split_bf(v, hi, lo);
        size_t o2 = (size_t)pp * 32 + j;
        g_x4h[o2] = hi; g_x4l[o2] = lo;
    }
}

// ---------------------------------------------------------------------------
// gemm1: g_ker2 = x4 @ Wg[par] + bg[par]
// ---------------------------------------------------------------------------
__global__ __launch_bounds__(256) void gemm1_kernel()
{
    __shared__ __align__(16) bf16 As[128 * 72];
    __shared__ __align__(16) bf16 Bs[128 * 72];

    const int tid = threadIdx.x;
    const int wid = tid >> 5, lane = tid & 31;
    const int gid = lane >> 2, tig = lane & 3;
    const int m0 = blockIdx.x * 128, n0g = blockIdx.y * 128;
    const int par = blockIdx.x >> 5;
    const int wm0 = (wid & 3) * 32, wn0 = (wid >> 2) * 64;

    const bf16* WgH = g_Wgh + (size_t)par * NG * 32;
    const bf16* WgL = g_Wgl + (size_t)par * NG * 32;

    for (int i = tid; i < 512; i += 256) {
        int r = i >> 2, q = (i & 3) * 8;
        *(uint4*)&As[r * 72 + q]      = *(const uint4*)&g_x4h[(size_t)(m0 + r) * 32 + q];
        *(uint4*)&As[r * 72 + 32 + q] = *(const uint4*)&g_x4l[(size_t)(m0 + r) * 32 + q];
        *(uint4*)&Bs[r * 72 + q]      = *(const uint4*)&WgH[(size_t)(n0g + r) * 32 + q];
        *(uint4*)&Bs[r * 72 + 32 + q] = *(const uint4*)&WgL[(size_t)(n0g + r) * 32 + q];
    }
    __syncthreads();

    float c[2][8][4];
    #pragma unroll
    for (int i = 0; i < 2; ++i)
        #pragma unroll
        for (int j = 0; j < 8; ++j)
            #pragma unroll
            for (int e = 0; e < 4; ++e) c[i][j][e] = 0.0f;

    #pragma unroll
    for (int combo = 0; combo < 3; ++combo) {
        const int aoff = (combo == 2) ? 32 : 0;
        const int boff = (combo == 1) ? 32 : 0;
        #pragma unroll
        for (int ks = 0; ks < 2; ++ks) {
            const int kb = ks * 16;
            uint32_t a[2][4];
            #pragma unroll
            for (int mf = 0; mf < 2; ++mf) {
                int row = wm0 + mf * 16 + gid;
                a[mf][0] = *(const uint32_t*)&As[row * 72       + aoff + kb + tig * 2];
                a[mf][1] = *(const uint32_t*)&As[(row + 8) * 72 + aoff + kb + tig * 2];
                a[mf][2] = *(const uint32_t*)&As[row * 72       + aoff + kb + tig * 2 + 8];
                a[mf][3] = *(const uint32_t*)&As[(row + 8) * 72 + aoff + kb + tig * 2 + 8];
            }
            uint32_t b[8][2];
            #pragma unroll
            for (int nf = 0; nf < 8; ++nf) {
                int n = wn0 + nf * 8 + gid;
                b[nf][0] = *(const uint32_t*)&Bs[n * 72 + boff + kb + tig * 2];
                b[nf][1] = *(const uint32_t*)&Bs[n * 72 + boff + kb + tig * 2 + 8];
            }
            #pragma unroll
            for (int mf = 0; mf < 2; ++mf)
                #pragma unroll
                for (int nf = 0; nf < 8; ++nf)
                    mma16816(c[mf][nf], a[mf], b[nf]);
        }
    }

    const float* bgp = g_bg + par * NG;
    #pragma unroll
    for (int mf = 0; mf < 2; ++mf) {
        int gm = m0 + wm0 + mf * 16 + gid;
        #pragma unroll
        for (int nf = 0; nf < 8; ++nf) {
            int gn = n0g + wn0 + nf * 8 + tig * 2;
            float bx = __ldg(&bgp[gn]), by = __ldg(&bgp[gn + 1]);
            float2 v0 = { c[mf][nf][0] + bx, c[mf][nf][1] + by };
            float2 v1 = { c[mf][nf][2] + bx, c[mf][nf][3] + by };
            *(float2*)&g_ker2[(size_t)gm * NG + gn]       = v0;
            *(float2*)&g_ker2[(size_t)(gm + 8) * NG + gn] = v1;
        }
    }
}

// ---------------------------------------------------------------------------
// fused gemm2 v2: pipelined. blockIdx.x = h*4 + b. CTA = one (b,h) row.
// Per 32-ch chunk: [stage next Xs/Bs] -> [build As] -> sync -> [MMA] -> sync.
// Dynamic smem: As 18KB | Bs 2x18KB | Xs 2x18KB  = 90KB.
// ---------------------------------------------------------------------------
#define SM_AS   0
#define SM_BS   18432
#define SM_XS   (18432 * 3)
#define SM_TOT  (18432 * 5)

__global__ __launch_bounds__(256, 2) void gemm2_fused2(
    const float* __restrict__ main_in,
    const float* __restrict__ bp, float* __restrict__ out)
{
    extern __shared__ __align__(16) uint8_t dsm[];
    bf16*  As = (bf16*)(dsm + SM_AS);
    bf16*  Bs = (bf16*)(dsm + SM_BS);     // 2 buffers of 9216 bf16
    float* Xs = (float*)(dsm + SM_XS);    // 2 buffers of 4608 floats

    const int tid = threadIdx.x;
    const int wid = tid >> 5, lane = tid & 31;
    const int gid = lane >> 2, tig = lane & 3;
    const int h = blockIdx.x >> 2, b = blockIdx.x & 3;
    const int m0 = b * 16384 + h * 128;
    const int wm0 = (wid & 3) * 32, wn0 = (wid >> 2) * 64;

    const int rA = (h - 1) >> 1, rB = (h + 1) >> 1;
    const bool vrA = h >= 1, vrB = h <= 126;

    // A-build identity: thread owns (w = tid>>1, 16 channels at ch0)
    const int aw  = tid >> 1;
    const int ch0 = (tid & 1) * 16;
    const int par = ((h & 1) << 1) | (aw & 1);
    const size_t pbase = ((size_t)par * 4096 + (h >> 1) * 64 + (aw >> 1)) * NG;
    const int cAq = (aw - 1) >> 1, cBq = (aw + 1) >> 1;
    const bool vcA = aw >= 1, vcB = aw <= 126;

    float c[2][8][4];
    #pragma unroll
    for (int i = 0; i < 2; ++i)
        #pragma unroll
        for (int j = 0; j < 8; ++j)
            #pragma unroll
            for (int e = 0; e < 4; ++e) c[i][j][e] = 0.0f;

    // ---- stage helper (macro-ish lambda) ----
    auto stage = [&](int buf, int kc) {
        float* Xb = Xs + buf * 4608;
        #pragma unroll
        for (int q = 0; q < 4; ++q) {
            int s = q * 256 + tid;           // 0..1023
            int r = s >> 9, col = (s >> 3) & 63, qq = s & 7;
            float4 v = make_float4(0.f, 0.f, 0.f, 0.f);
            if (r ? vrB : vrA) {
                int srow = r ? rB : rA;
                v = *(const float4*)&main_in[(((size_t)b * 64 + srow) * 64 + col) * CC + kc + qq * 4];
            }
            *(float4*)&Xb[(r * 64 + col) * 36 + qq * 4] = v;
        }
        bf16* Bb = Bs + buf * 9216;
        #pragma unroll
        for (int q = 0; q < 4; ++q) {
            int s = q * 256 + tid;           // 0..1023
            int plane = s >> 9, n = (s >> 2) & 127, part = s & 3;
            const bf16* src = plane ? g_WpTl : g_WpTh;
            uint4 v = *(const uint4*)&src[(size_t)n * CC + kc + part * 8];
            *(uint4*)&Bb[n * 72 + plane * 32 + part * 8] = v;
        }
    };

    stage(0, 0);
    __syncthreads();

    for (int chunk = 0; chunk < 8; ++chunk) {
        const int cur = chunk & 1;
        const int kc  = chunk * 32;

        if (chunk < 7) stage(cur ^ 1, kc + 32);

        // ---- build As (128 x 32ch hi + 32ch lo) from Xs[cur] + ker2 ----
        {
            const float* Xb = Xs + cur * 4608;
            #pragma unroll
            for (int half = 0; half < 2; ++half) {
                const int cc = ch0 + half * 8;          // local ch 0..31
                const float* kbp = g_ker2 + pbase + kc + cc;
                float ks[4][8], ss[4][8];
                #pragma unroll
                for (int g = 0; g < 4; ++g) {
                    *(float4*)&ks[g][0] = *(const float4*)&kbp[g * 256];
                    *(float4*)&ks[g][4] = *(const float4*)&kbp[g * 256 + 4];
                }
                #pragma unroll
                for (int g = 0; g < 4; ++g) {
                    int  rr  = g >> 1;
                    int  col = (g & 1) ? cBq : cAq;
                    bool ok  = (g & 1) ? vcB : vcA;
                    float4 va = make_float4(0.f, 0.f, 0.f, 0.f), vb = va;
                    if (ok) {
                        va = *(const float4*)&Xb[(rr * 64 + col) * 36 + cc];
                        vb = *(const float4*)&Xb[(rr * 64 + col) * 36 + cc + 4];
                    }
                    *(float4*)&ss[g][0] = va;
                    *(float4*)&ss[g][4] = vb;
                }
                uint32_t hu[4], lu[4];
                #pragma unroll
                for (int j2 = 0; j2 < 4; ++j2) {
                    float y0 = ks[0][j2*2]   * ss[0][j2*2]   + ks[1][j2*2]   * ss[1][j2*2]
                             + ks[2][j2*2]   * ss[2][j2*2]   + ks[3][j2*2]   * ss[3][j2*2];
                    float y1 = ks[0][j2*2+1] * ss[0][j2*2+1] + ks[1][j2*2+1] * ss[1][j2*2+1]
                             + ks[2][j2*2+1] * ss[2][j2*2+1] + ks[3][j2*2+1] * ss[3][j2*2+1];
                    bf16 h0, l0, h1, l1;
                    split_bf(y0, h0, l0);
                    split_bf(y1, h1, l1);
                    hu[j2] = (uint32_t)__bfloat16_as_ushort(h0) | ((uint32_t)__bfloat16_as_ushort(h1) << 16);
                    lu[j2] = (uint32_t)__bfloat16_as_ushort(l0) | ((uint32_t)__bfloat16_as_ushort(l1) << 16);
                }
                *(uint4*)&As[aw * 72 + cc]      = make_uint4(hu[0], hu[1], hu[2], hu[3]);
                *(uint4*)&As[aw * 72 + 32 + cc] = make_uint4(lu[0], lu[1], lu[2], lu[3]);
            }
        }
        __syncthreads();

        // ---- MMA on As, Bs[cur] ----
        {
            const bf16* Bb = Bs + cur * 9216;
            #pragma unroll
            for (int combo = 0; combo < 3; ++combo) {
                const int aoff = (combo == 2) ? 32 : 0;
                const int boff = (combo == 1) ? 32 : 0;
                #pragma unroll
                for (int ks2 = 0; ks2 < 2; ++ks2) {
                    const int kb = ks2 * 16;
                    uint32_t a[2][4];
                    #pragma unroll
                    for (int mf = 0; mf < 2; ++mf) {
                        int row = wm0 + mf * 16 + gid;
                        a[mf][0] = *(const uint32_t*)&As[row * 72       + aoff + kb + tig * 2];
                        a[mf][1] = *(const uint32_t*)&As[(row + 8) * 72 + aoff + kb + tig * 2];
                        a[mf][2] = *(const uint32_t*)&As[row * 72       + aoff + kb + tig * 2 + 8];
                        a[mf][3] = *(const uint32_t*)&As[(row + 8) * 72 + aoff + kb + tig * 2 + 8];
                    }
                    uint32_t bfr[8][2];
                    #pragma unroll
                    for (int nf = 0; nf < 8; ++nf) {
                        int n = wn0 + nf * 8 + gid;
                        bfr[nf][0] = *(const uint32_t*)&Bb[n * 72 + boff + kb + tig * 2];
                        bfr[nf][1] = *(const uint32_t*)&Bb[n * 72 + boff + kb + tig * 2 + 8];
                    }
                    #pragma unroll
                    for (int mf = 0; mf < 2; ++mf)
                        #pragma unroll
                        for (int nf = 0; nf < 8; ++nf)
                            mma16816(c[mf][nf], a[mf], bfr[nf]);
                }
            }
        }
        __syncthreads();
    }

    #pragma unroll
    for (int mf = 0; mf < 2; ++mf) {
        int gm = m0 + wm0 + mf * 16 + gid;
        #pragma unroll
        for (int nf = 0; nf < 8; ++nf) {
            int gn = wn0 + nf * 8 + tig * 2;
            float bx = __ldg(&bp[gn]), by = __ldg(&bp[gn + 1]);
            float2 v0 = { c[mf][nf][0] + bx, c[mf][nf][1] + by };
            float2 v1 = { c[mf][nf][2] + bx, c[mf][nf][3] + by };
            *(float2*)&out[(size_t)gm * FF + gn]       = v0;
            *(float2*)&out[(size_t)(gm + 8) * FF + gn] = v1;
        }
    }
}

// ---------------------------------------------------------------------------
extern "C" void kernel_launch(void* const* d_in, const int* in_sizes, int n_in,
                              void* d_out, int out_size)
{
    const float* main_in = (const float*)d_in[0];
    const float* W1 = (const float*)d_in[2];
    const float* b1 = (const float*)d_in[3];
    const float* W2 = (const float*)d_in[4];
    const float* b2 = (const float*)d_in[5];
    const float* W3 = (const float*)d_in[6];
    const float* b3 = (const float*)d_in[7];
    const float* W4 = (const float*)d_in[8];
    const float* b4 = (const float*)d_in[9];
    const float* Wo = (const float*)d_in[10];
    const float* bo = (const float*)d_in[11];
    const float* Wp = (const float*)d_in[12];
    const float* bp = (const float*)d_in[13];
    float* out = (float*)d_out;

    cudaFuncSetAttribute(gemm2_fused2, cudaFuncAttributeMaxDynamicSharedMemorySize, SM_TOT);

    const int prep_elems = 4 * NG * 32 + 4 * NG + FF * CC + 4096 + 4096 + 32;
    prep_kernel<<<(prep_elems + 255) / 256, 256>>>(Wo, bo, Wp, W1, b1);
    mlp_kernel<<<1024, 256>>>(W2, b2, W3, b3, W4, b4);
    gemm1_kernel<<<dim3(128, 8), 256>>>();
    gemm2_fused2<<<512, 256, SM_TOT>>>(main_in, bp, out);
}

// round 8
// speedup vs baseline: 1.0889x; 1.0652x over previous
#include <cuda_runtime.h>
#include <cuda_bf16.h>
#include <cstdint>
#include <math.h>

#define HT   128
#define CC   256
#define FF   128
#define BB   4
#define NU   32
#define NOUT 2304
#define NG   1024
#define PIF  3.14159265358979323846f

typedef __nv_bfloat16 bf16;

// ---------------- scratch globals ----------------
__device__ __align__(16) bf16  g_Wgh[4 * NG * 32];
__device__ __align__(16) bf16  g_Wgl[4 * NG * 32];
__device__ __align__(16) float g_bg[4 * NG];
__device__ __align__(16) float g_Hc[128 * 32];
__device__ __align__(16) float g_Wc[128 * 32];
__device__ __align__(16) float g_Cc[32];
__device__ __align__(16) bf16  g_x4h[(size_t)16384 * 32];
__device__ __align__(16) bf16  g_x4l[(size_t)16384 * 32];
__device__ __align__(16) bf16  g_WpTh[(size_t)FF * CC];
__device__ __align__(16) bf16  g_WpTl[(size_t)FF * CC];
__device__ __align__(16) float g_ker2[(size_t)16384 * NG];   // [p'][g*256+c]

__device__ __forceinline__ void split_bf(float v, bf16& hi, bf16& lo) {
    hi = __float2bfloat16(v);
    lo = __float2bfloat16(v - __bfloat162float(hi));
}
__device__ __forceinline__ void mma16816(float c[4], const uint32_t a[4], const uint32_t b[2]) {
    asm volatile(
        "mma.sync.aligned.m16n8k16.row.col.f32.bf16.bf16.f32 "
        "{%0,%1,%2,%3}, {%4,%5,%6,%7}, {%8,%9}, {%0,%1,%2,%3};"
        : "+f"(c[0]), "+f"(c[1]), "+f"(c[2]), "+f"(c[3])
        : "r"(a[0]), "r"(a[1]), "r"(a[2]), "r"(a[3]), "r"(b[0]), "r"(b[1]));
}
__device__ __forceinline__ int grp(int t, int par) { return (t == 0) ? 0 : (t == 2) ? 1 : (par ? 0 : 1); }

__device__ __forceinline__ void cp16(uint32_t dst, const void* src, int sz) {
    asm volatile("cp.async.cg.shared.global [%0], [%1], 16, %2;"
                 :: "r"(dst), "l"(src), "r"(sz));
}
#define CP_COMMIT() asm volatile("cp.async.commit_group;" ::: "memory")
#define CP_WAIT0()  asm volatile("cp.async.wait_group 0;" ::: "memory")

// ---------------------------------------------------------------------------
// prep
// ---------------------------------------------------------------------------
__global__ __launch_bounds__(256) void prep_kernel(
    const float* __restrict__ Wo, const float* __restrict__ bo,
    const float* __restrict__ Wp,
    const float* __restrict__ W1, const float* __restrict__ b1)
{
    int idx = blockIdx.x * 256 + threadIdx.x;
    if (idx < 4 * NG * 32) {
        int par = idx >> 15, rem = idx & 32767;
        int n = rem >> 5, k = rem & 31;
        int g = n >> 8, c = n & 255, gr = g >> 1, gc = g & 1;
        int ph = par >> 1, pw = par & 1;
        float s = 0.0f;
        #pragma unroll
        for (int tr = 0; tr < 3; ++tr)
            #pragma unroll
            for (int tc = 0; tc < 3; ++tc)
                if (grp(tr, ph) == gr && grp(tc, pw) == gc)
                    s += Wo[(size_t)k * NOUT + (tr * 3 + tc) * 256 + c];
        bf16 hi, lo; split_bf(s, hi, lo);
        g_Wgh[idx] = hi; g_Wgl[idx] = lo;
    } else if ((idx -= 4 * NG * 32) < 4 * NG) {
        int par = idx >> 10, n = idx & 1023;
        int g = n >> 8, c = n & 255, gr = g >> 1, gc = g & 1;
        int ph = par >> 1, pw = par & 1;
        float s = 0.0f;
        #pragma unroll
        for (int tr = 0; tr < 3; ++tr)
            #pragma unroll
            for (int tc = 0; tc < 3; ++tc)
                if (grp(tr, ph) == gr && grp(tc, pw) == gc)
                    s += bo[(tr * 3 + tc) * 256 + c];
        g_bg[idx] = s;
    } else if ((idx -= 4 * NG) < FF * CC) {
        int n = idx >> 8, k = idx & 255;
        bf16 hi, lo; split_bf(Wp[(size_t)k * FF + n], hi, lo);
        g_WpTh[idx] = hi; g_WpTl[idx] = lo;
    } else if ((idx -= FF * CC) < 4096) {
        int h = idx >> 5, j = idx & 31;
        float s = 0.0f;
        for (int i = 0; i < 25; ++i) {
            float f = 1.0f + (float)i * (1.0f / 24.0f);
            s += cosf(PIF * (2.0f * h * (1.0f / 127.0f) + 1.0f) * f) * W1[i * 32 + j];
        }
        g_Hc[idx] = s;
    } else if ((idx -= 4096) < 4096) {
        int w = idx >> 5, j = idx & 31;
        float s = 0.0f;
        for (int i = 0; i < 25; ++i) {
            float f = 1.0f + (float)i * (1.0f / 24.0f);
            s += cosf(PIF * (2.0f * w * (1.0f / 127.0f) + 1.0f) * f) * W1[(25 + i) * 32 + j];
        }
        g_Wc[idx] = s;
    } else if ((idx -= 4096) < 32) {
        int j = idx;
        float s = b1[j];
        for (int i = 0; i < 50; ++i) {
            float f = 1.0f + (float)(i % 25) * (1.0f / 24.0f);
            s += cosf(PIF * 5.0f * f) * W1[(50 + i) * 32 + j];
        }
        for (int i = 100; i < 118; ++i) s -= W1[i * 32 + j];
        g_Cc[j] = s;
    }
}

// ---------------------------------------------------------------------------
// mlp -> x4 hi/lo, parity-major p'
// ---------------------------------------------------------------------------
__global__ __launch_bounds__(256) void mlp_kernel(
    const float* __restrict__ W2, const float* __restrict__ b2,
    const float* __restrict__ W3, const float* __restrict__ b3,
    const float* __restrict__ W4, const float* __restrict__ b4)
{
    __shared__ float xa[16][32];
    __shared__ float xb[16][32];
    const int tid = threadIdx.x;
    const int pix0 = blockIdx.x * 16;

    for (int o = tid; o < 512; o += 256) {
        int p = o >> 5, j = o & 31;
        int pix = pix0 + p, h = pix >> 7, w = pix & 127;
        xa[p][j] = fmaxf(g_Hc[h * 32 + j] + g_Wc[w * 32 + j] + g_Cc[j], 0.0f);
    }
    __syncthreads();
    for (int o = tid; o < 512; o += 256) {
        int p = o >> 5, j = o & 31;
        float s = b2[j];
        #pragma unroll
        for (int k = 0; k < NU; ++k) s += xa[p][k] * W2[k * NU + j];
        xb[p][j] = fmaxf(s, 0.0f);
    }
    __syncthreads();
    for (int o = tid; o < 512; o += 256) {
        int p = o >> 5, j = o & 31;
        float s = b3[j];
        #pragma unroll
        for (int k = 0; k < NU; ++k) s += xb[p][k] * W3[k * NU + j];
        xa[p][j] = fmaxf(s, 0.0f);
    }
    __syncthreads();
    for (int o = tid; o < 512; o += 256) {
        int p = o >> 5, j = o & 31;
        float s = b4[j];
        #pragma unroll
        for (int k = 0; k < NU; ++k) s += xa[p][k] * W4[k * NU + j];
        float v = fmaxf(s, 0.0f);
        int pix = pix0 + p, h = pix >> 7, w = pix & 127;
        int pp = (((h & 1) << 1) | (w & 1)) * 4096 + (h >> 1) * 64 + (w >> 1);
        bf16 hi, lo; split_bf(v, hi, lo);
        size_t o2 = (size_t)pp * 32 + j;
        g_x4h[o2] = hi; g_x4l[o2] = lo;
    }
}

// ---------------------------------------------------------------------------
// gemm1: g_ker2 = x4 @ Wg[par] + bg[par]  (frag-hoisted combos)
// ---------------------------------------------------------------------------
__global__ __launch_bounds__(256) void gemm1_kernel()
{
    __shared__ __align__(16) bf16 As[128 * 72];
    __shared__ __align__(16) bf16 Bs[128 * 72];

    const int tid = threadIdx.x;
    const int wid = tid >> 5, lane = tid & 31;
    const int gid = lane >> 2, tig = lane & 3;
    const int m0 = blockIdx.x * 128, n0g = blockIdx.y * 128;
    const int par = blockIdx.x >> 5;
    const int wm0 = (wid & 3) * 32, wn0 = (wid >> 2) * 64;

    const bf16* WgH = g_Wgh + (size_t)par * NG * 32;
    const bf16* WgL = g_Wgl + (size_t)par * NG * 32;

    for (int i = tid; i < 512; i += 256) {
        int r = i >> 2, q = (i & 3) * 8;
        *(uint4*)&As[r * 72 + q]      = *(const uint4*)&g_x4h[(size_t)(m0 + r) * 32 + q];
        *(uint4*)&As[r * 72 + 32 + q] = *(const uint4*)&g_x4l[(size_t)(m0 + r) * 32 + q];
        *(uint4*)&Bs[r * 72 + q]      = *(const uint4*)&WgH[(size_t)(n0g + r) * 32 + q];
        *(uint4*)&Bs[r * 72 + 32 + q] = *(const uint4*)&WgL[(size_t)(n0g + r) * 32 + q];
    }
    __syncthreads();

    float c[2][8][4];
    #pragma unroll
    for (int i = 0; i < 2; ++i)
        #pragma unroll
        for (int j = 0; j < 8; ++j)
            #pragma unroll
            for (int e = 0; e < 4; ++e) c[i][j][e] = 0.0f;

    #pragma unroll
    for (int ks = 0; ks < 2; ++ks) {
        const int kb = ks * 16;
        uint32_t aH[2][4], aL[2][4], bH[8][2], bL[8][2];
        #pragma unroll
        for (int mf = 0; mf < 2; ++mf) {
            int row = wm0 + mf * 16 + gid;
            aH[mf][0] = *(const uint32_t*)&As[row * 72       + kb + tig * 2];
            aH[mf][1] = *(const uint32_t*)&As[(row + 8) * 72 + kb + tig * 2];
            aH[mf][2] = *(const uint32_t*)&As[row * 72       + kb + tig * 2 + 8];
            aH[mf][3] = *(const uint32_t*)&As[(row + 8) * 72 + kb + tig * 2 + 8];
            aL[mf][0] = *(const uint32_t*)&As[row * 72       + 32 + kb + tig * 2];
            aL[mf][1] = *(const uint32_t*)&As[(row + 8) * 72 + 32 + kb + tig * 2];
            aL[mf][2] = *(const uint32_t*)&As[row * 72       + 32 + kb + tig * 2 + 8];
            aL[mf][3] = *(const uint32_t*)&As[(row + 8) * 72 + 32 + kb + tig * 2 + 8];
        }
        #pragma unroll
        for (int nf = 0; nf < 8; ++nf) {
            int n = wn0 + nf * 8 + gid;
            bH[nf][0] = *(const uint32_t*)&Bs[n * 72 + kb + tig * 2];
            bH[nf][1] = *(const uint32_t*)&Bs[n * 72 + kb + tig * 2 + 8];
            bL[nf][0] = *(const uint32_t*)&Bs[n * 72 + 32 + kb + tig * 2];
            bL[nf][1] = *(const uint32_t*)&Bs[n * 72 + 32 + kb + tig * 2 + 8];
        }
        #pragma unroll
        for (int mf = 0; mf < 2; ++mf)
            #pragma unroll
            for (int nf = 0; nf < 8; ++nf) {
                mma16816(c[mf][nf], aH[mf], bH[nf]);
                mma16816(c[mf][nf], aH[mf], bL[nf]);
                mma16816(c[mf][nf], aL[mf], bH[nf]);
            }
    }

    const float* bgp = g_bg + par * NG;
    #pragma unroll
    for (int mf = 0; mf < 2; ++mf) {
        int gm = m0 + wm0 + mf * 16 + gid;
        #pragma unroll
        for (int nf = 0; nf < 8; ++nf) {
            int gn = n0g + wn0 + nf * 8 + tig * 2;
            float bx = __ldg(&bgp[gn]), by = __ldg(&bgp[gn + 1]);
            float2 v0 = { c[mf][nf][0] + bx, c[mf][nf][1] + by };
            float2 v1 = { c[mf][nf][2] + bx, c[mf][nf][3] + by };
            *(float2*)&g_ker2[(size_t)gm * NG + gn]       = v0;
            *(float2*)&g_ker2[(size_t)(gm + 8) * NG + gn] = v1;
        }
    }
}

// ---------------------------------------------------------------------------
// fused gemm2 v3: cp.async staging + frag-hoisted combos.
// blockIdx.x = h*4 + b. Per chunk: [build As] sync [cp.async stage(next) + MMA] wait sync.
// smem: As 18KB | Bs 2x18KB | Xs 2x18KB = 90KB.
// ---------------------------------------------------------------------------
#define SM_AS   0
#define SM_BS   18432
#define SM_XS   (18432 * 3)
#define SM_TOT  (18432 * 5)

__global__ __launch_bounds__(256, 2) void gemm2_fused3(
    const float* __restrict__ main_in,
    const float* __restrict__ bp, float* __restrict__ out)
{
    extern __shared__ __align__(16) uint8_t dsm[];
    bf16*  As = (bf16*)(dsm + SM_AS);
    bf16*  Bs = (bf16*)(dsm + SM_BS);
    float* Xs = (float*)(dsm + SM_XS);
    const uint32_t smb = (uint32_t)__cvta_generic_to_shared(dsm);

    const int tid = threadIdx.x;
    const int wid = tid >> 5, lane = tid & 31;
    const int gid = lane >> 2, tig = lane & 3;
    const int h = blockIdx.x >> 2, b = blockIdx.x & 3;
    const int m0 = b * 16384 + h * 128;
    const int wm0 = (wid & 3) * 32, wn0 = (wid >> 2) * 64;

    const int rA = (h - 1) >> 1, rB = (h + 1) >> 1;
    const bool vrA = h >= 1, vrB = h <= 126;

    const int aw  = tid >> 1;
    const int ch0 = (tid & 1) * 16;
    const int par = ((h & 1) << 1) | (aw & 1);
    const size_t pbase = ((size_t)par * 4096 + (h >> 1) * 64 + (aw >> 1)) * NG;
    const int cAq = (aw - 1) >> 1, cBq = (aw + 1) >> 1;
    const bool vcA = aw >= 1, vcB = aw <= 126;

    float c[2][8][4];
    #pragma unroll
    for (int i = 0; i < 2; ++i)
        #pragma unroll
        for (int j = 0; j < 8; ++j)
            #pragma unroll
            for (int e = 0; e < 4; ++e) c[i][j][e] = 0.0f;

    // ---- async stage of chunk kc into buffer buf ----
    auto stage = [&](int buf, int kc) {
        // Xs: 2 src rows x 64 cols x 32 ch
        #pragma unroll
        for (int q = 0; q < 4; ++q) {
            int s = q * 256 + tid;
            int r = s >> 9, col = (s >> 3) & 63, qq = s & 7;
            bool ok  = r ? vrB : vrA;
            int srow = r ? rB : rA;
            if (srow < 0) srow = 0;
            const float* src = &main_in[(((size_t)b * 64 + srow) * 64 + col) * CC + kc + qq * 4];
            uint32_t dst = smb + SM_XS + (uint32_t)(buf * 4608 + (r * 64 + col) * 36 + qq * 4) * 4;
            cp16(dst, src, ok ? 16 : 0);
        }
        // Bs: Wp hi/lo 128n x 32k
        #pragma unroll
        for (int q = 0; q < 4; ++q) {
            int s = q * 256 + tid;
            int plane = s >> 9, n = (s >> 2) & 127, part = s & 3;
            const bf16* src = (plane ? g_WpTl : g_WpTh) + (size_t)n * CC + kc + part * 8;
            uint32_t dst = smb + SM_BS + (uint32_t)(buf * 9216 + n * 72 + plane * 32 + part * 8) * 2;
            cp16(dst, src, 16);
        }
        CP_COMMIT();
    };

    stage(0, 0);
    CP_WAIT0();
    __syncthreads();

    for (int chunk = 0; chunk < 8; ++chunk) {
        const int cur = chunk & 1;
        const int kc  = chunk * 32;

        // ---- build As from Xs[cur] + ker2 ----
        {
            const float* Xb = Xs + cur * 4608;
            #pragma unroll
            for (int half = 0; half < 2; ++half) {
                const int cc = ch0 + half * 8;
                const float* kbp = g_ker2 + pbase + kc + cc;
                float ks[4][8], ss[4][8];
                #pragma unroll
                for (int g = 0; g < 4; ++g) {
                    *(float4*)&ks[g][0] = *(const float4*)&kbp[g * 256];
                    *(float4*)&ks[g][4] = *(const float4*)&kbp[g * 256 + 4];
                }
                #pragma unroll
                for (int g = 0; g < 4; ++g) {
                    int  rr  = g >> 1;
                    int  col = (g & 1) ? cBq : cAq;
                    bool ok  = (g & 1) ? vcB : vcA;
                    float4 va = make_float4(0.f, 0.f, 0.f, 0.f), vb = va;
                    if (ok) {
                        va = *(const float4*)&Xb[(rr * 64 + col) * 36 + cc];
                        vb = *(const float4*)&Xb[(rr * 64 + col) * 36 + cc + 4];
                    }
                    *(float4*)&ss[g][0] = va;
                    *(float4*)&ss[g][4] = vb;
                }
                uint32_t hu[4], lu[4];
                #pragma unroll
                for (int j2 = 0; j2 < 4; ++j2) {
                    float y0 = ks[0][j2*2]   * ss[0][j2*2]   + ks[1][j2*2]   * ss[1][j2*2]
                             + ks[2][j2*2]   * ss[2][j2*2]   + ks[3][j2*2]   * ss[3][j2*2];
                    float y1 = ks[0][j2*2+1] * ss[0][j2*2+1] + ks[1][j2*2+1] * ss[1][j2*2+1]
                             + ks[2][j2*2+1] * ss[2][j2*2+1] + ks[3][j2*2+1] * ss[3][j2*2+1];
                    bf16 h0, l0, h1, l1;
                    split_bf(y0, h0, l0);
                    split_bf(y1, h1, l1);
                    hu[j2] = (uint32_t)__bfloat16_as_ushort(h0) | ((uint32_t)__bfloat16_as_ushort(h1) << 16);
                    lu[j2] = (uint32_t)__bfloat16_as_ushort(l0) | ((uint32_t)__bfloat16_as_ushort(l1) << 16);
                }
                *(uint4*)&As[aw * 72 + cc]      = make_uint4(hu[0], hu[1], hu[2], hu[3]);
                *(uint4*)&As[aw * 72 + 32 + cc] = make_uint4(lu[0], lu[1], lu[2], lu[3]);
            }
        }
        __syncthreads();

        // ---- stage next (async) + MMA ----
        if (chunk < 7) stage(cur ^ 1, kc + 32);
        {
            const bf16* Bb = Bs + cur * 9216;
            #pragma unroll
            for (int ks2 = 0; ks2 < 2; ++ks2) {
                const int kb = ks2 * 16;
                uint32_t aH[2][4], aL[2][4], bH[8][2], bL[8][2];
                #pragma unroll
                for (int mf = 0; mf < 2; ++mf) {
                    int row = wm0 + mf * 16 + gid;
                    aH[mf][0] = *(const uint32_t*)&As[row * 72       + kb + tig * 2];
                    aH[mf][1] = *(const uint32_t*)&As[(row + 8) * 72 + kb + tig * 2];
                    aH[mf][2] = *(const uint32_t*)&As[row * 72       + kb + tig * 2 + 8];
                    aH[mf][3] = *(const uint32_t*)&As[(row + 8) * 72 + kb + tig * 2 + 8];
                    aL[mf][0] = *(const uint32_t*)&As[row * 72       + 32 + kb + tig * 2];
                    aL[mf][1] = *(const uint32_t*)&As[(row + 8) * 72 + 32 + kb + tig * 2];
                    aL[mf][2] = *(const uint32_t*)&As[row * 72       + 32 + kb + tig * 2 + 8];
                    aL[mf][3] = *(const uint32_t*)&As[(row + 8) * 72 + 32 + kb + tig * 2 + 8];
                }
                #pragma unroll
                for (int nf = 0; nf < 8; ++nf) {
                    int n = wn0 + nf * 8 + gid;
                    bH[nf][0] = *(const uint32_t*)&Bb[n * 72 + kb + tig * 2];
                    bH[nf][1] = *(const uint32_t*)&Bb[n * 72 + kb + tig * 2 + 8];
                    bL[nf][0] = *(const uint32_t*)&Bb[n * 72 + 32 + kb + tig * 2];
                    bL[nf][1] = *(const uint32_t*)&Bb[n * 72 + 32 + kb + tig * 2 + 8];
                }
                #pragma unroll
                for (int mf = 0; mf < 2; ++mf)
                    #pragma unroll
                    for (int nf = 0; nf < 8; ++nf) {
                        mma16816(c[mf][nf], aH[mf], bH[nf]);
                        mma16816(c[mf][nf], aH[mf], bL[nf]);
                        mma16816(c[mf][nf], aL[mf], bH[nf]);
                    }
            }
        }
        CP_WAIT0();
        __syncthreads();
    }

    #pragma unroll
    for (int mf = 0; mf < 2; ++mf) {
        int gm = m0 + wm0 + mf * 16 + gid;
        #pragma unroll
        for (int nf = 0; nf < 8; ++nf) {
            int gn = wn0 + nf * 8 + tig * 2;
            float bx = __ldg(&bp[gn]), by = __ldg(&bp[gn + 1]);
            float2 v0 = { c[mf][nf][0] + bx, c[mf][nf][1] + by };
            float2 v1 = { c[mf][nf][2] + bx, c[mf][nf][3] + by };
            *(float2*)&out[(size_t)gm * FF + gn]       = v0;
            *(float2*)&out[(size_t)(gm + 8) * FF + gn] = v1;
        }
    }
}

// ---------------------------------------------------------------------------
extern "C" void kernel_launch(void* const* d_in, const int* in_sizes, int n_in,
                              void* d_out, int out_size)
{
    const float* main_in = (const float*)d_in[0];
    const float* W1 = (const float*)d_in[2];
    const float* b1 = (const float*)d_in[3];
    const float* W2 = (const float*)d_in[4];
    const float* b2 = (const float*)d_in[5];
    const float* W3 = (const float*)d_in[6];
    const float* b3 = (const float*)d_in[7];
    const float* W4 = (const float*)d_in[8];
    const float* b4 = (const float*)d_in[9];
    const float* Wo = (const float*)d_in[10];
    const float* bo = (const float*)d_in[11];
    const float* Wp = (const float*)d_in[12];
    const float* bp = (const float*)d_in[13];
    float* out = (float*)d_out;

    cudaFuncSetAttribute(gemm2_fused3, cudaFuncAttributeMaxDynamicSharedMemorySize, SM_TOT);

    const int prep_elems = 4 * NG * 32 + 4 * NG + FF * CC + 4096 + 4096 + 32;
    prep_kernel<<<(prep_elems + 255) / 256, 256>>>(Wo, bo, Wp, W1, b1);
    mlp_kernel<<<1024, 256>>>(W2, b2, W3, b3, W4, b4);
    gemm1_kernel<<<dim3(128, 8), 256>>>();
    gemm2_fused3<<<512, 256, SM_TOT>>>(main_in, bp, out);
}

// round 9
// speedup vs baseline: 1.1168x; 1.0256x over previous
#include <cuda_runtime.h>
#include <cuda_bf16.h>
#include <cstdint>
#include <math.h>

#define HT   128
#define CC   256
#define FF   128
#define BB   4
#define NU   32
#define NOUT 2304
#define NG   1024
#define PIF  3.14159265358979323846f

typedef __nv_bfloat16 bf16;

// ---------------- scratch globals ----------------
__device__ __align__(16) bf16  g_Wgh[4 * NG * 32];
__device__ __align__(16) bf16  g_Wgl[4 * NG * 32];
__device__ __align__(16) float g_bg[4 * NG];
__device__ __align__(16) float g_Hc[128 * 32];
__device__ __align__(16) float g_Wc[128 * 32];
__device__ __align__(16) float g_Cc[32];
__device__ __align__(16) bf16  g_x4h[(size_t)16384 * 32];
__device__ __align__(16) bf16  g_x4l[(size_t)16384 * 32];
__device__ __align__(16) bf16  g_WpTh[(size_t)FF * CC];
__device__ __align__(16) bf16  g_WpTl[(size_t)FF * CC];
__device__ __align__(16) float g_ker2[(size_t)16384 * NG];   // [p'][g*256+c]

__device__ __forceinline__ void split_bf(float v, bf16& hi, bf16& lo) {
    hi = __float2bfloat16(v);
    lo = __float2bfloat16(v - __bfloat162float(hi));
}
__device__ __forceinline__ void mma16816(float c[4], const uint32_t a[4], const uint32_t b[2]) {
    asm volatile(
        "mma.sync.aligned.m16n8k16.row.col.f32.bf16.bf16.f32 "
        "{%0,%1,%2,%3}, {%4,%5,%6,%7}, {%8,%9}, {%0,%1,%2,%3};"
        : "+f"(c[0]), "+f"(c[1]), "+f"(c[2]), "+f"(c[3])
        : "r"(a[0]), "r"(a[1]), "r"(a[2]), "r"(a[3]), "r"(b[0]), "r"(b[1]));
}
__device__ __forceinline__ void ldsm_x4(uint32_t& r0, uint32_t& r1, uint32_t& r2, uint32_t& r3,
                                        uint32_t addr) {
    asm volatile("ldmatrix.sync.aligned.m8n8.x4.shared.b16 {%0,%1,%2,%3}, [%4];"
                 : "=r"(r0), "=r"(r1), "=r"(r2), "=r"(r3) : "r"(addr));
}
__device__ __forceinline__ int grp(int t, int par) { return (t == 0) ? 0 : (t == 2) ? 1 : (par ? 0 : 1); }

__device__ __forceinline__ void cp16(uint32_t dst, const void* src, int sz) {
    asm volatile("cp.async.cg.shared.global [%0], [%1], 16, %2;"
                 :: "r"(dst), "l"(src), "r"(sz));
}
#define CP_COMMIT() asm volatile("cp.async.commit_group;" ::: "memory")
#define CP_WAIT0()  asm volatile("cp.async.wait_group 0;" ::: "memory")

// ---------------------------------------------------------------------------
// prep
// ---------------------------------------------------------------------------
__global__ __launch_bounds__(256) void prep_kernel(
    const float* __restrict__ Wo, const float* __restrict__ bo,
    const float* __restrict__ Wp,
    const float* __restrict__ W1, const float* __restrict__ b1)
{
    int idx = blockIdx.x * 256 + threadIdx.x;
    if (idx < 4 * NG * 32) {
        int par = idx >> 15, rem = idx & 32767;
        int n = rem >> 5, k = rem & 31;
        int g = n >> 8, c = n & 255, gr = g >> 1, gc = g & 1;
        int ph = par >> 1, pw = par & 1;
        float s = 0.0f;
        #pragma unroll
        for (int tr = 0; tr < 3; ++tr)
            #pragma unroll
            for (int tc = 0; tc < 3; ++tc)
                if (grp(tr, ph) == gr && grp(tc, pw) == gc)
                    s += Wo[(size_t)k * NOUT + (tr * 3 + tc) * 256 + c];
        bf16 hi, lo; split_bf(s, hi, lo);
        g_Wgh[idx] = hi; g_Wgl[idx] = lo;
    } else if ((idx -= 4 * NG * 32) < 4 * NG) {
        int par = idx >> 10, n = idx & 1023;
        int g = n >> 8, c = n & 255, gr = g >> 1, gc = g & 1;
        int ph = par >> 1, pw = par & 1;
        float s = 0.0f;
        #pragma unroll
        for (int tr = 0; tr < 3; ++tr)
            #pragma unroll
            for (int tc = 0; tc < 3; ++tc)
                if (grp(tr, ph) == gr && grp(tc, pw) == gc)
                    s += bo[(tr * 3 + tc) * 256 + c];
        g_bg[idx] = s;
    } else if ((idx -= 4 * NG) < FF * CC) {
        int n = idx >> 8, k = idx & 255;
        bf16 hi, lo; split_bf(Wp[(size_t)k * FF + n], hi, lo);
        g_WpTh[idx] = hi; g_WpTl[idx] = lo;
    } else if ((idx -= FF * CC) < 4096) {
        int h = idx >> 5, j = idx & 31;
        float s = 0.0f;
        for (int i = 0; i < 25; ++i) {
            float f = 1.0f + (float)i * (1.0f / 24.0f);
            s += cosf(PIF * (2.0f * h * (1.0f / 127.0f) + 1.0f) * f) * W1[i * 32 + j];
        }
        g_Hc[idx] = s;
    } else if ((idx -= 4096) < 4096) {
        int w = idx >> 5, j = idx & 31;
        float s = 0.0f;
        for (int i = 0; i < 25; ++i) {
            float f = 1.0f + (float)i * (1.0f / 24.0f);
            s += cosf(PIF * (2.0f * w * (1.0f / 127.0f) + 1.0f) * f) * W1[(25 + i) * 32 + j];
        }
        g_Wc[idx] = s;
    } else if ((idx -= 4096) < 32) {
        int j = idx;
        float s = b1[j];
        for (int i = 0; i < 50; ++i) {
            float f = 1.0f + (float)(i % 25) * (1.0f / 24.0f);
            s += cosf(PIF * 5.0f * f) * W1[(50 + i) * 32 + j];
        }
        for (int i = 100; i < 118; ++i) s -= W1[i * 32 + j];
        g_Cc[j] = s;
    }
}

// ---------------------------------------------------------------------------
// mlp -> x4 hi/lo, parity-major p'
// ---------------------------------------------------------------------------
__global__ __launch_bounds__(256) void mlp_kernel(
    const float* __restrict__ W2, const float* __restrict__ b2,
    const float* __restrict__ W3, const float* __restrict__ b3,
    const float* __restrict__ W4, const float* __restrict__ b4)
{
    __shared__ float xa[16][32];
    __shared__ float xb[16][32];
    const int tid = threadIdx.x;
    const int pix0 = blockIdx.x * 16;

    for (int o = tid; o < 512; o += 256) {
        int p = o >> 5, j = o & 31;
        int pix = pix0 + p, h = pix >> 7, w = pix & 127;
        xa[p][j] = fmaxf(g_Hc[h * 32 + j] + g_Wc[w * 32 + j] + g_Cc[j], 0.0f);
    }
    __syncthreads();
    for (int o = tid; o < 512; o += 256) {
        int p = o >> 5, j = o & 31;
        float s = b2[j];
        #pragma unroll
        for (int k = 0; k < NU; ++k) s += xa[p][k] * W2[k * NU + j];
        xb[p][j] = fmaxf(s, 0.0f);
    }
    __syncthreads();
    for (int o = tid; o < 512; o += 256) {
        int p = o >> 5, j = o & 31;
        float s = b3[j];
        #pragma unroll
        for (int k = 0; k < NU; ++k) s += xb[p][k] * W3[k * NU + j];
        xa[p][j] = fmaxf(s, 0.0f);
    }
    __syncthreads();
    for (int o = tid; o < 512; o += 256) {
        int p = o >> 5, j = o & 31;
        float s = b4[j];
        #pragma unroll
        for (int k = 0; k < NU; ++k) s += xa[p][k] * W4[k * NU + j];
        float v = fmaxf(s, 0.0f);
        int pix = pix0 + p, h = pix >> 7, w = pix & 127;
        int pp = (((h & 1) << 1) | (w & 1)) * 4096 + (h >> 1) * 64 + (w >> 1);
        bf16 hi, lo; split_bf(v, hi, lo);
        size_t o2 = (size_t)pp * 32 + j;
        g_x4h[o2] = hi; g_x4l[o2] = lo;
    }
}

// ---------------------------------------------------------------------------
// gemm1: g_ker2 = x4 @ Wg[par] + bg[par]  (LDSM fragments)
// ---------------------------------------------------------------------------
__global__ __launch_bounds__(256) void gemm1_kernel()
{
    __shared__ __align__(16) bf16 As[128 * 72];
    __shared__ __align__(16) bf16 Bs[128 * 72];

    const int tid = threadIdx.x;
    const int wid = tid >> 5, lane = tid & 31;
    const int gid = lane >> 2, tig = lane & 3;
    const int m0 = blockIdx.x * 128, n0g = blockIdx.y * 128;
    const int par = blockIdx.x >> 5;
    const int wm0 = (wid & 3) * 32, wn0 = (wid >> 2) * 64;

    const bf16* WgH = g_Wgh + (size_t)par * NG * 32;
    const bf16* WgL = g_Wgl + (size_t)par * NG * 32;

    for (int i = tid; i < 512; i += 256) {
        int r = i >> 2, q = (i & 3) * 8;
        *(uint4*)&As[r * 72 + q]      = *(const uint4*)&g_x4h[(size_t)(m0 + r) * 32 + q];
        *(uint4*)&As[r * 72 + 32 + q] = *(const uint4*)&g_x4l[(size_t)(m0 + r) * 32 + q];
        *(uint4*)&Bs[r * 72 + q]      = *(const uint4*)&WgH[(size_t)(n0g + r) * 32 + q];
        *(uint4*)&Bs[r * 72 + 32 + q] = *(const uint4*)&WgL[(size_t)(n0g + r) * 32 + q];
    }
    __syncthreads();

    const uint32_t smA = (uint32_t)__cvta_generic_to_shared(As);
    const uint32_t smB = (uint32_t)__cvta_generic_to_shared(Bs);
    // lane -> ldmatrix address components
    const int aRow = (lane & 7) + ((lane >> 3) & 1) * 8;   // + row quad
    const int aCol = ((lane >> 4) & 1) * 8;                // + col quad
    const int bRow = (lane & 7) + ((lane >> 4) & 1) * 8;
    const int bCol = ((lane >> 3) & 1) * 8;

    float c[2][8][4];
    #pragma unroll
    for (int i = 0; i < 2; ++i)
        #pragma unroll
        for (int j = 0; j < 8; ++j)
            #pragma unroll
            for (int e = 0; e < 4; ++e) c[i][j][e] = 0.0f;

    #pragma unroll
    for (int ks = 0; ks < 2; ++ks) {
        const int kb = ks * 16;
        uint32_t aH[2][4], aL[2][4], bH[8][2], bL[8][2];
        #pragma unroll
        for (int mf = 0; mf < 2; ++mf) {
            uint32_t adr = smA + (uint32_t)((wm0 + mf * 16 + aRow) * 72 + kb + aCol) * 2;
            ldsm_x4(aH[mf][0], aH[mf][1], aH[mf][2], aH[mf][3], adr);
            ldsm_x4(aL[mf][0], aL[mf][1], aL[mf][2], aL[mf][3], adr + 64);
        }
        #pragma unroll
        for (int nf = 0; nf < 8; nf += 2) {
            uint32_t adr = smB + (uint32_t)((wn0 + nf * 8 + bRow) * 72 + kb + bCol) * 2;
            ldsm_x4(bH[nf][0], bH[nf][1], bH[nf + 1][0], bH[nf + 1][1], adr);
            ldsm_x4(bL[nf][0], bL[nf][1], bL[nf + 1][0], bL[nf + 1][1], adr + 64);
        }
        #pragma unroll
        for (int mf = 0; mf < 2; ++mf)
            #pragma unroll
            for (int nf = 0; nf < 8; ++nf) {
                mma16816(c[mf][nf], aH[mf], bH[nf]);
                mma16816(c[mf][nf], aH[mf], bL[nf]);
                mma16816(c[mf][nf], aL[mf], bH[nf]);
            }
    }

    const float* bgp = g_bg + par * NG;
    #pragma unroll
    for (int mf = 0; mf < 2; ++mf) {
        int gm = m0 + wm0 + mf * 16 + gid;
        #pragma unroll
        for (int nf = 0; nf < 8; ++nf) {
            int gn = n0g + wn0 + nf * 8 + tig * 2;
            float bx = __ldg(&bgp[gn]), by = __ldg(&bgp[gn + 1]);
            float2 v0 = { c[mf][nf][0] + bx, c[mf][nf][1] + by };
            float2 v1 = { c[mf][nf][2] + bx, c[mf][nf][3] + by };
            *(float2*)&g_ker2[(size_t)gm * NG + gn]       = v0;
            *(float2*)&g_ker2[(size_t)(gm + 8) * NG + gn] = v1;
        }
    }
}

// ---------------------------------------------------------------------------
// fused gemm2 v4: cp.async staging + LDSM fragments.
// blockIdx.x = h*4 + b. Per chunk: [build As] sync [cp.async stage(next) + MMA] wait sync.
// smem: As 18KB | Bs 2x18KB | Xs 2x18KB = 90KB.
// ---------------------------------------------------------------------------
#define SM_AS   0
#define SM_BS   18432
#define SM_XS   (18432 * 3)
#define SM_TOT  (18432 * 5)

__global__ __launch_bounds__(256, 2) void gemm2_fused4(
    const float* __restrict__ main_in,
    const float* __restrict__ bp, float* __restrict__ out)
{
    extern __shared__ __align__(16) uint8_t dsm[];
    bf16*  As = (bf16*)(dsm + SM_AS);
    float* Xs = (float*)(dsm + SM_XS);
    const uint32_t smb = (uint32_t)__cvta_generic_to_shared(dsm);

    const int tid = threadIdx.x;
    const int wid = tid >> 5, lane = tid & 31;
    const int gid = lane >> 2, tig = lane & 3;
    const int h = blockIdx.x >> 2, b = blockIdx.x & 3;
    const int m0 = b * 16384 + h * 128;
    const int wm0 = (wid & 3) * 32, wn0 = (wid >> 2) * 64;

    const int rA = (h - 1) >> 1, rB = (h + 1) >> 1;
    const bool vrA = h >= 1, vrB = h <= 126;

    const int aw  = tid >> 1;
    const int ch0 = (tid & 1) * 16;
    const int par = ((h & 1) << 1) | (aw & 1);
    const size_t pbase = ((size_t)par * 4096 + (h >> 1) * 64 + (aw >> 1)) * NG;
    const int cAq = (aw - 1) >> 1, cBq = (aw + 1) >> 1;
    const bool vcA = aw >= 1, vcB = aw <= 126;

    const int aRow = (lane & 7) + ((lane >> 3) & 1) * 8;
    const int aCol = ((lane >> 4) & 1) * 8;
    const int bRow = (lane & 7) + ((lane >> 4) & 1) * 8;
    const int bCol = ((lane >> 3) & 1) * 8;

    float c[2][8][4];
    #pragma unroll
    for (int i = 0; i < 2; ++i)
        #pragma unroll
        for (int j = 0; j < 8; ++j)
            #pragma unroll
            for (int e = 0; e < 4; ++e) c[i][j][e] = 0.0f;

    auto stage = [&](int buf, int kc) {
        #pragma unroll
        for (int q = 0; q < 4; ++q) {
            int s = q * 256 + tid;
            int r = s >> 9, col = (s >> 3) & 63, qq = s & 7;
            bool ok  = r ? vrB : vrA;
            int srow = r ? rB : rA;
            if (srow < 0) srow = 0;
            const float* src = &main_in[(((size_t)b * 64 + srow) * 64 + col) * CC + kc + qq * 4];
            uint32_t dst = smb + SM_XS + (uint32_t)(buf * 4608 + (r * 64 + col) * 36 + qq * 4) * 4;
            cp16(dst, src, ok ? 16 : 0);
        }
        #pragma unroll
        for (int q = 0; q < 4; ++q) {
            int s = q * 256 + tid;
            int plane = s >> 9, n = (s >> 2) & 127, part = s & 3;
            const bf16* src = (plane ? g_WpTl : g_WpTh) + (size_t)n * CC + kc + part * 8;
            uint32_t dst = smb + SM_BS + (uint32_t)(buf * 9216 + n * 72 + plane * 32 + part * 8) * 2;
            cp16(dst, src, 16);
        }
        CP_COMMIT();
    };

    stage(0, 0);
    CP_WAIT0();
    __syncthreads();

    for (int chunk = 0; chunk < 8; ++chunk) {
        const int cur = chunk & 1;
        const int kc  = chunk * 32;

        // ---- build As from Xs[cur] + ker2 ----
        {
            const float* Xb = Xs + cur * 4608;
            #pragma unroll
            for (int half = 0; half < 2; ++half) {
                const int cc = ch0 + half * 8;
                const float* kbp = g_ker2 + pbase + kc + cc;
                float ks[4][8], ss[4][8];
                #pragma unroll
                for (int g = 0; g < 4; ++g) {
                    *(float4*)&ks[g][0] = *(const float4*)&kbp[g * 256];
                    *(float4*)&ks[g][4] = *(const float4*)&kbp[g * 256 + 4];
                }
                #pragma unroll
                for (int g = 0; g < 4; ++g) {
                    int  rr  = g >> 1;
                    int  col = (g & 1) ? cBq : cAq;
                    bool ok  = (g & 1) ? vcB : vcA;
                    float4 va = make_float4(0.f, 0.f, 0.f, 0.f), vb = va;
                    if (ok) {
                        va = *(const float4*)&Xb[(rr * 64 + col) * 36 + cc];
                        vb = *(const float4*)&Xb[(rr * 64 + col) * 36 + cc + 4];
                    }
                    *(float4*)&ss[g][0] = va;
                    *(float4*)&ss[g][4] = vb;
                }
                uint32_t hu[4], lu[4];
                #pragma unroll
                for (int j2 = 0; j2 < 4; ++j2) {
                    float y0 = ks[0][j2*2]   * ss[0][j2*2]   + ks[1][j2*2]   * ss[1][j2*2]
                             + ks[2][j2*2]   * ss[2][j2*2]   + ks[3][j2*2]   * ss[3][j2*2];
                    float y1 = ks[0][j2*2+1] * ss[0][j2*2+1] + ks[1][j2*2+1] * ss[1][j2*2+1]
                             + ks[2][j2*2+1] * ss[2][j2*2+1] + ks[3][j2*2+1] * ss[3][j2*2+1];
                    bf16 h0, l0, h1, l1;
                    split_bf(y0, h0, l0);
                    split_bf(y1, h1, l1);
                    hu[j2] = (uint32_t)__bfloat16_as_ushort(h0) | ((uint32_t)__bfloat16_as_ushort(h1) << 16);
                    lu[j2] = (uint32_t)__bfloat16_as_ushort(l0) | ((uint32_t)__bfloat16_as_ushort(l1) << 16);
                }
                *(uint4*)&As[aw * 72 + cc]      = make_uint4(hu[0], hu[1], hu[2], hu[3]);
                *(uint4*)&As[aw * 72 + 32 + cc] = make_uint4(lu[0], lu[1], lu[2], lu[3]);
            }
        }
        __syncthreads();

        // ---- stage next (async) + MMA ----
        if (chunk < 7) stage(cur ^ 1, kc + 32);
        {
            const uint32_t smBb = smb + SM_BS + (uint32_t)(cur * 9216) * 2;
            const uint32_t smAa = smb + SM_AS;
            #pragma unroll
            for (int ks2 = 0; ks2 < 2; ++ks2) {
                const int kb = ks2 * 16;
                uint32_t aH[2][4], aL[2][4], bH[8][2], bL[8][2];
                #pragma unroll
                for (int mf = 0; mf < 2; ++mf) {
                    uint32_t adr = smAa + (uint32_t)((wm0 + mf * 16 + aRow) * 72 + kb + aCol) * 2;
                    ldsm_x4(aH[mf][0], aH[mf][1], aH[mf][2], aH[mf][3], adr);
                    ldsm_x4(aL[mf][0], aL[mf][1], aL[mf][2], aL[mf][3], adr + 64);
                }
                #pragma unroll
                for (int nf = 0; nf < 8; nf += 2) {
                    uint32_t adr = smBb + (uint32_t)((wn0 + nf * 8 + bRow) * 72 + kb + bCol) * 2;
                    ldsm_x4(bH[nf][0], bH[nf][1], bH[nf + 1][0], bH[nf + 1][1], adr);
                    ldsm_x4(bL[nf][0], bL[nf][1], bL[nf + 1][0], bL[nf + 1][1], adr + 64);
                }
                #pragma unroll
                for (int mf = 0; mf < 2; ++mf)
                    #pragma unroll
                    for (int nf = 0; nf < 8; ++nf) {
                        mma16816(c[mf][nf], aH[mf], bH[nf]);
                        mma16816(c[mf][nf], aH[mf], bL[nf]);
                        mma16816(c[mf][nf], aL[mf], bH[nf]);
                    }
            }
        }
        CP_WAIT0();
        __syncthreads();
    }

    #pragma unroll
    for (int mf = 0; mf < 2; ++mf) {
        int gm = m0 + wm0 + mf * 16 + gid;
        #pragma unroll
        for (int nf = 0; nf < 8; ++nf) {
            int gn = wn0 + nf * 8 + tig * 2;
            float bx = __ldg(&bp[gn]), by = __ldg(&bp[gn + 1]);
            float2 v0 = { c[mf][nf][0] + bx, c[mf][nf][1] + by };
            float2 v1 = { c[mf][nf][2] + bx, c[mf][nf][3] + by };
            *(float2*)&out[(size_t)gm * FF + gn]       = v0;
            *(float2*)&out[(size_t)(gm + 8) * FF + gn] = v1;
        }
    }
}

// ---------------------------------------------------------------------------
extern "C" void kernel_launch(void* const* d_in, const int* in_sizes, int n_in,
                              void* d_out, int out_size)
{
    const float* main_in = (const float*)d_in[0];
    const float* W1 = (const float*)d_in[2];
    const float* b1 = (const float*)d_in[3];
    const float* W2 = (const float*)d_in[4];
    const float* b2 = (const float*)d_in[5];
    const float* W3 = (const float*)d_in[6];
    const float* b3 = (const float*)d_in[7];
    const float* W4 = (const float*)d_in[8];
    const float* b4 = (const float*)d_in[9];
    const float* Wo = (const float*)d_in[10];
    const float* bo = (const float*)d_in[11];
    const float* Wp = (const float*)d_in[12];
    const float* bp = (const float*)d_in[13];
    float* out = (float*)d_out;

    cudaFuncSetAttribute(gemm2_fused4, cudaFuncAttributeMaxDynamicSharedMemorySize, SM_TOT);

    const int prep_elems = 4 * NG * 32 + 4 * NG + FF * CC + 4096 + 4096 + 32;
    prep_kernel<<<(prep_elems + 255) / 256, 256>>>(Wo, bo, Wp, W1, b1);
    mlp_kernel<<<1024, 256>>>(W2, b2, W3, b3, W4, b4);
    gemm1_kernel<<<dim3(128, 8), 256>>>();
    gemm2_fused4<<<512, 256, SM_TOT>>>(main_in, bp, out);
}

// round 10
// speedup vs baseline: 1.1532x; 1.0325x over previous
#include <cuda_runtime.h>
#include <cuda_bf16.h>
#include <cstdint>
#include <math.h>

#define HT   128
#define CC   256
#define FF   128
#define BB   4
#define NU   32
#define NOUT 2304
#define NG   1024
#define PIF  3.14159265358979323846f

typedef __nv_bfloat16 bf16;

// ---------------- scratch globals ----------------
__device__ __align__(16) bf16  g_Wgh[4 * NG * 32];
__device__ __align__(16) bf16  g_Wgl[4 * NG * 32];
__device__ __align__(16) float g_bg[4 * NG];
__device__ __align__(16) float g_Hc[128 * 32];
__device__ __align__(16) float g_Wc[128 * 32];
__device__ __align__(16) float g_Cc[32];
__device__ __align__(16) bf16  g_x4h[(size_t)16384 * 32];
__device__ __align__(16) bf16  g_x4l[(size_t)16384 * 32];
__device__ __align__(16) bf16  g_WpTh[(size_t)FF * CC];
__device__ __align__(16) bf16  g_WpTl[(size_t)FF * CC];
__device__ __align__(16) float g_ker2[(size_t)16384 * NG];   // [p'][g*256+c]

__device__ __forceinline__ void split_bf(float v, bf16& hi, bf16& lo) {
    hi = __float2bfloat16(v);
    lo = __float2bfloat16(v - __bfloat162float(hi));
}
__device__ __forceinline__ void mma16816(float c[4], const uint32_t a[4], const uint32_t b[2]) {
    asm volatile(
        "mma.sync.aligned.m16n8k16.row.col.f32.bf16.bf16.f32 "
        "{%0,%1,%2,%3}, {%4,%5,%6,%7}, {%8,%9}, {%0,%1,%2,%3};"
        : "+f"(c[0]), "+f"(c[1]), "+f"(c[2]), "+f"(c[3])
        : "r"(a[0]), "r"(a[1]), "r"(a[2]), "r"(a[3]), "r"(b[0]), "r"(b[1]));
}
__device__ __forceinline__ void ldsm_x4(uint32_t& r0, uint32_t& r1, uint32_t& r2, uint32_t& r3,
                                        uint32_t addr) {
    asm volatile("ldmatrix.sync.aligned.m8n8.x4.shared.b16 {%0,%1,%2,%3}, [%4];"
                 : "=r"(r0), "=r"(r1), "=r"(r2), "=r"(r3) : "r"(addr));
}
__device__ __forceinline__ int grp(int t, int par) { return (t == 0) ? 0 : (t == 2) ? 1 : (par ? 0 : 1); }

__device__ __forceinline__ void cp16(uint32_t dst, const void* src, int sz) {
    asm volatile("cp.async.cg.shared.global [%0], [%1], 16, %2;"
                 :: "r"(dst), "l"(src), "r"(sz));
}
#define CP_COMMIT() asm volatile("cp.async.commit_group;" ::: "memory")
#define CP_WAIT0()  asm volatile("cp.async.wait_group 0;" ::: "memory")

// ---------------------------------------------------------------------------
// prep
// ---------------------------------------------------------------------------
__global__ __launch_bounds__(256) void prep_kernel(
    const float* __restrict__ Wo, const float* __restrict__ bo,
    const float* __restrict__ Wp,
    const float* __restrict__ W1, const float* __restrict__ b1)
{
    int idx = blockIdx.x * 256 + threadIdx.x;
    if (idx < 4 * NG * 32) {
        int par = idx >> 15, rem = idx & 32767;
        int n = rem >> 5, k = rem & 31;
        int g = n >> 8, c = n & 255, gr = g >> 1, gc = g & 1;
        int ph = par >> 1, pw = par & 1;
        float s = 0.0f;
        #pragma unroll
        for (int tr = 0; tr < 3; ++tr)
            #pragma unroll
            for (int tc = 0; tc < 3; ++tc)
                if (grp(tr, ph) == gr && grp(tc, pw) == gc)
                    s += Wo[(size_t)k * NOUT + (tr * 3 + tc) * 256 + c];
        bf16 hi, lo; split_bf(s, hi, lo);
        g_Wgh[idx] = hi; g_Wgl[idx] = lo;
    } else if ((idx -= 4 * NG * 32) < 4 * NG) {
        int par = idx >> 10, n = idx & 1023;
        int g = n >> 8, c = n & 255, gr = g >> 1, gc = g & 1;
        int ph = par >> 1, pw = par & 1;
        float s = 0.0f;
        #pragma unroll
        for (int tr = 0; tr < 3; ++tr)
            #pragma unroll
            for (int tc = 0; tc < 3; ++tc)
                if (grp(tr, ph) == gr && grp(tc, pw) == gc)
                    s += bo[(tr * 3 + tc) * 256 + c];
        g_bg[idx] = s;
    } else if ((idx -= 4 * NG) < FF * CC) {
        int n = idx >> 8, k = idx & 255;
        bf16 hi, lo; split_bf(Wp[(size_t)k * FF + n], hi, lo);
        g_WpTh[idx] = hi; g_WpTl[idx] = lo;
    } else if ((idx -= FF * CC) < 4096) {
        int h = idx >> 5, j = idx & 31;
        float s = 0.0f;
        for (int i = 0; i < 25; ++i) {
            float f = 1.0f + (float)i * (1.0f / 24.0f);
            s += cosf(PIF * (2.0f * h * (1.0f / 127.0f) + 1.0f) * f) * W1[i * 32 + j];
        }
        g_Hc[idx] = s;
    } else if ((idx -= 4096) < 4096) {
        int w = idx >> 5, j = idx & 31;
        float s = 0.0f;
        for (int i = 0; i < 25; ++i) {
            float f = 1.0f + (float)i * (1.0f / 24.0f);
            s += cosf(PIF * (2.0f * w * (1.0f / 127.0f) + 1.0f) * f) * W1[(25 + i) * 32 + j];
        }
        g_Wc[idx] = s;
    } else if ((idx -= 4096) < 32) {
        int j = idx;
        float s = b1[j];
        for (int i = 0; i < 50; ++i) {
            float f = 1.0f + (float)(i % 25) * (1.0f / 24.0f);
            s += cosf(PIF * 5.0f * f) * W1[(50 + i) * 32 + j];
        }
        for (int i = 100; i < 118; ++i) s -= W1[i * 32 + j];
        g_Cc[j] = s;
    }
}

// ---------------------------------------------------------------------------
// mlp -> x4 hi/lo, parity-major p'
// ---------------------------------------------------------------------------
__global__ __launch_bounds__(256) void mlp_kernel(
    const float* __restrict__ W2, const float* __restrict__ b2,
    const float* __restrict__ W3, const float* __restrict__ b3,
    const float* __restrict__ W4, const float* __restrict__ b4)
{
    __shared__ float xa[16][32];
    __shared__ float xb[16][32];
    const int tid = threadIdx.x;
    const int pix0 = blockIdx.x * 16;

    for (int o = tid; o < 512; o += 256) {
        int p = o >> 5, j = o & 31;
        int pix = pix0 + p, h = pix >> 7, w = pix & 127;
        xa[p][j] = fmaxf(g_Hc[h * 32 + j] + g_Wc[w * 32 + j] + g_Cc[j], 0.0f);
    }
    __syncthreads();
    for (int o = tid; o < 512; o += 256) {
        int p = o >> 5, j = o & 31;
        float s = b2[j];
        #pragma unroll
        for (int k = 0; k < NU; ++k) s += xa[p][k] * W2[k * NU + j];
        xb[p][j] = fmaxf(s, 0.0f);
    }
    __syncthreads();
    for (int o = tid; o < 512; o += 256) {
        int p = o >> 5, j = o & 31;
        float s = b3[j];
        #pragma unroll
        for (int k = 0; k < NU; ++k) s += xb[p][k] * W3[k * NU + j];
        xa[p][j] = fmaxf(s, 0.0f);
    }
    __syncthreads();
    for (int o = tid; o < 512; o += 256) {
        int p = o >> 5, j = o & 31;
        float s = b4[j];
        #pragma unroll
        for (int k = 0; k < NU; ++k) s += xa[p][k] * W4[k * NU + j];
        float v = fmaxf(s, 0.0f);
        int pix = pix0 + p, h = pix >> 7, w = pix & 127;
        int pp = (((h & 1) << 1) | (w & 1)) * 4096 + (h >> 1) * 64 + (w >> 1);
        bf16 hi, lo; split_bf(v, hi, lo);
        size_t o2 = (size_t)pp * 32 + j;
        g_x4h[o2] = hi; g_x4l[o2] = lo;
    }
}

// ---------------------------------------------------------------------------
// gemm1: g_ker2 = x4 @ Wg[par] + bg[par]  (LDSM fragments)
// ---------------------------------------------------------------------------
__global__ __launch_bounds__(256) void gemm1_kernel()
{
    __shared__ __align__(16) bf16 As[128 * 72];
    __shared__ __align__(16) bf16 Bs[128 * 72];

    const int tid = threadIdx.x;
    const int wid = tid >> 5, lane = tid & 31;
    const int gid = lane >> 2, tig = lane & 3;
    const int m0 = blockIdx.x * 128, n0g = blockIdx.y * 128;
    const int par = blockIdx.x >> 5;
    const int wm0 = (wid & 3) * 32, wn0 = (wid >> 2) * 64;

    const bf16* WgH = g_Wgh + (size_t)par * NG * 32;
    const bf16* WgL = g_Wgl + (size_t)par * NG * 32;

    for (int i = tid; i < 512; i += 256) {
        int r = i >> 2, q = (i & 3) * 8;
        *(uint4*)&As[r * 72 + q]      = *(const uint4*)&g_x4h[(size_t)(m0 + r) * 32 + q];
        *(uint4*)&As[r * 72 + 32 + q] = *(const uint4*)&g_x4l[(size_t)(m0 + r) * 32 + q];
        *(uint4*)&Bs[r * 72 + q]      = *(const uint4*)&WgH[(size_t)(n0g + r) * 32 + q];
        *(uint4*)&Bs[r * 72 + 32 + q] = *(const uint4*)&WgL[(size_t)(n0g + r) * 32 + q];
    }
    __syncthreads();

    const uint32_t smA = (uint32_t)__cvta_generic_to_shared(As);
    const uint32_t smB = (uint32_t)__cvta_generic_to_shared(Bs);
    const int aRow = (lane & 7) + ((lane >> 3) & 1) * 8;
    const int aCol = ((lane >> 4) & 1) * 8;
    const int bRow = (lane & 7) + ((lane >> 4) & 1) * 8;
    const int bCol = ((lane >> 3) & 1) * 8;

    float c[2][8][4];
    #pragma unroll
    for (int i = 0; i < 2; ++i)
        #pragma unroll
        for (int j = 0; j < 8; ++j)
            #pragma unroll
            for (int e = 0; e < 4; ++e) c[i][j][e] = 0.0f;

    #pragma unroll
    for (int ks = 0; ks < 2; ++ks) {
        const int kb = ks * 16;
        uint32_t aH[2][4], aL[2][4], bH[8][2], bL[8][2];
        #pragma unroll
        for (int mf = 0; mf < 2; ++mf) {
            uint32_t adr = smA + (uint32_t)((wm0 + mf * 16 + aRow) * 72 + kb + aCol) * 2;
            ldsm_x4(aH[mf][0], aH[mf][1], aH[mf][2], aH[mf][3], adr);
            ldsm_x4(aL[mf][0], aL[mf][1], aL[mf][2], aL[mf][3], adr + 64);
        }
        #pragma unroll
        for (int nf = 0; nf < 8; nf += 2) {
            uint32_t adr = smB + (uint32_t)((wn0 + nf * 8 + bRow) * 72 + kb + bCol) * 2;
            ldsm_x4(bH[nf][0], bH[nf][1], bH[nf + 1][0], bH[nf + 1][1], adr);
            ldsm_x4(bL[nf][0], bL[nf][1], bL[nf + 1][0], bL[nf + 1][1], adr + 64);
        }
        #pragma unroll
        for (int mf = 0; mf < 2; ++mf)
            #pragma unroll
            for (int nf = 0; nf < 8; ++nf) {
                mma16816(c[mf][nf], aH[mf], bH[nf]);
                mma16816(c[mf][nf], aH[mf], bL[nf]);
                mma16816(c[mf][nf], aL[mf], bH[nf]);
            }
    }

    const float* bgp = g_bg + par * NG;
    #pragma unroll
    for (int mf = 0; mf < 2; ++mf) {
        int gm = m0 + wm0 + mf * 16 + gid;
        #pragma unroll
        for (int nf = 0; nf < 8; ++nf) {
            int gn = n0g + wn0 + nf * 8 + tig * 2;
            float bx = __ldg(&bgp[gn]), by = __ldg(&bgp[gn + 1]);
            float2 v0 = { c[mf][nf][0] + bx, c[mf][nf][1] + by };
            float2 v1 = { c[mf][nf][2] + bx, c[mf][nf][3] + by };
            *(float2*)&g_ker2[(size_t)gm * NG + gn]       = v0;
            *(float2*)&g_ker2[(size_t)(gm + 8) * NG + gn] = v1;
        }
    }
}

// ---------------------------------------------------------------------------
// fused gemm2 v5: half-row CTAs (64 m), 3 CTAs/SM target.
// blockIdx.x = ((h*4)+b)*2 + whalf. smem 64.2KB, <=85 regs.
// ---------------------------------------------------------------------------
#define SM_AS   0
#define SM_BS   9216
#define SM_XS   (9216 + 36864)
#define SM_TOT  (9216 + 36864 + 19584)
#define XS_FLTS 2448   // 2 rows * 34 cols * 36 stride

__global__ __launch_bounds__(256, 3) void gemm2_fused5(
    const float* __restrict__ main_in,
    const float* __restrict__ bp, float* __restrict__ out)
{
    extern __shared__ __align__(16) uint8_t dsm[];
    bf16*  As = (bf16*)(dsm + SM_AS);
    float* Xs = (float*)(dsm + SM_XS);
    const uint32_t smb = (uint32_t)__cvta_generic_to_shared(dsm);

    const int tid = threadIdx.x;
    const int wid = tid >> 5, lane = tid & 31;
    const int gid = lane >> 2, tig = lane & 3;

    const int bx = blockIdx.x;
    const int whalf = bx & 1;
    const int b = (bx >> 1) & 3;
    const int h = bx >> 3;
    const int w0 = whalf * 64;
    const int c0 = whalf ? 31 : 0;            // first staged src col

    const int wm = (wid & 3) * 16;            // warp m offset (4 m-warps)
    const int wn = (wid >> 2) * 64;           // warp n offset (2 n-warps)

    const int rA = (h - 1) >> 1, rB = (h + 1) >> 1;
    const bool vrA = h >= 1, vrB = h <= 126;

    // A-build identity: thread owns (local w = tid>>2, 8 channels at ch0)
    const int awl = tid >> 2;
    const int w   = w0 + awl;
    const int ch0 = (tid & 3) * 8;
    const int par = ((h & 1) << 1) | (w & 1);
    const size_t pbase = ((size_t)par * 4096 + (h >> 1) * 64 + (w >> 1)) * NG;
    const int colA = ((w - 1) >> 1) - c0, colB = ((w + 1) >> 1) - c0;
    const bool vcA = w >= 1, vcB = w <= 126;

    const int aRow = (lane & 7) + ((lane >> 3) & 1) * 8;
    const int aCol = ((lane >> 4) & 1) * 8;
    const int bRow = (lane & 7) + ((lane >> 4) & 1) * 8;
    const int bCol = ((lane >> 3) & 1) * 8;

    float c[8][4];
    #pragma unroll
    for (int j = 0; j < 8; ++j)
        #pragma unroll
        for (int e = 0; e < 4; ++e) c[j][e] = 0.0f;

    auto stage = [&](int buf, int kc) {
        // Xs: 2 src rows x 34 cols x 32 ch  (544 cp16)
        #pragma unroll
        for (int q = 0; q < 3; ++q) {
            int s = q * 256 + tid;
            if (s < 544) {
                int pos = s >> 3, qq = s & 7;
                int r = pos / 34, ci = pos - r * 34;
                int col = c0 + ci;
                bool ok = (r ? vrB : vrA) && (col < 64);
                int srow = r ? rB : rA; if (srow < 0) srow = 0;
                int scol = ok ? col : 0;
                const float* src = &main_in[(((size_t)b * 64 + srow) * 64 + scol) * CC + kc + qq * 4];
                uint32_t dst = smb + SM_XS + (uint32_t)(buf * XS_FLTS + pos * 36 + qq * 4) * 4;
                cp16(dst, src, ok ? 16 : 0);
            }
        }
        // Bs: Wp hi/lo 128n x 32k (1024 cp16)
        #pragma unroll
        for (int q = 0; q < 4; ++q) {
            int s = q * 256 + tid;
            int plane = s >> 9, n = (s >> 2) & 127, part = s & 3;
            const bf16* src = (plane ? g_WpTl : g_WpTh) + (size_t)n * CC + kc + part * 8;
            uint32_t dst = smb + SM_BS + (uint32_t)(buf * 9216 + n * 72 + plane * 32 + part * 8) * 2;
            cp16(dst, src, 16);
        }
        CP_COMMIT();
    };

    stage(0, 0);
    CP_WAIT0();
    __syncthreads();

    for (int chunk = 0; chunk < 8; ++chunk) {
        const int cur = chunk & 1;
        const int kc  = chunk * 32;

        // ---- build As (64w x 32ch hi+lo): progressive accumulation, low regs ----
        {
            const float* Xb = Xs + cur * XS_FLTS;
            const float* kbp = g_ker2 + pbase + kc + ch0;
            float y[8];
            #pragma unroll
            for (int j = 0; j < 8; ++j) y[j] = 0.0f;
            #pragma unroll
            for (int g = 0; g < 4; ++g) {
                float4 k0 = *(const float4*)&kbp[g * 256];
                float4 k1 = *(const float4*)&kbp[g * 256 + 4];
                int  rr  = g >> 1;
                int  cr  = (g & 1) ? colB : colA;
                bool ok  = (g & 1) ? vcB : vcA;
                float4 s0 = make_float4(0.f, 0.f, 0.f, 0.f), s1 = s0;
                if (ok) {
                    s0 = *(const float4*)&Xb[(rr * 34 + cr) * 36 + ch0];
                    s1 = *(const float4*)&Xb[(rr * 34 + cr) * 36 + ch0 + 4];
                }
                y[0] += k0.x * s0.x; y[1] += k0.y * s0.y;
                y[2] += k0.z * s0.z; y[3] += k0.w * s0.w;
                y[4] += k1.x * s1.x; y[5] += k1.y * s1.y;
                y[6] += k1.z * s1.z; y[7] += k1.w * s1.w;
            }
            uint32_t hu[4], lu[4];
            #pragma unroll
            for (int j2 = 0; j2 < 4; ++j2) {
                bf16 h0, l0, h1, l1;
                split_bf(y[j2 * 2], h0, l0);
                split_bf(y[j2 * 2 + 1], h1, l1);
                hu[j2] = (uint32_t)__bfloat16_as_ushort(h0) | ((uint32_t)__bfloat16_as_ushort(h1) << 16);
                lu[j2] = (uint32_t)__bfloat16_as_ushort(l0) | ((uint32_t)__bfloat16_as_ushort(l1) << 16);
            }
            *(uint4*)&As[awl * 72 + ch0]      = make_uint4(hu[0], hu[1], hu[2], hu[3]);
            *(uint4*)&As[awl * 72 + 32 + ch0] = make_uint4(lu[0], lu[1], lu[2], lu[3]);
        }
        __syncthreads();

        // ---- stage next (async) + MMA ----
        if (chunk < 7) stage(cur ^ 1, kc + 32);
        {
            const uint32_t smAa = smb + SM_AS;
            const uint32_t smBb = smb + SM_BS + (uint32_t)(cur * 9216) * 2;
            #pragma unroll
            for (int ks2 = 0; ks2 < 2; ++ks2) {
                const int kb = ks2 * 16;
                uint32_t aH[4], aL[4];
                {
                    uint32_t adr = smAa + (uint32_t)((wm + aRow) * 72 + kb + aCol) * 2;
                    ldsm_x4(aH[0], aH[1], aH[2], aH[3], adr);
                    ldsm_x4(aL[0], aL[1], aL[2], aL[3], adr + 64);
                }
                #pragma unroll
                for (int nf = 0; nf < 8; nf += 2) {
                    uint32_t b0H[2], b1H[2], b0L[2], b1L[2];
                    uint32_t adr = smBb + (uint32_t)((wn + nf * 8 + bRow) * 72 + kb + bCol) * 2;
                    ldsm_x4(b0H[0], b0H[1], b1H[0], b1H[1], adr);
                    ldsm_x4(b0L[0], b0L[1], b1L[0], b1L[1], adr + 64);
                    mma16816(c[nf],     aH, b0H);
                    mma16816(c[nf],     aH, b0L);
                    mma16816(c[nf],     aL, b0H);
                    mma16816(c[nf + 1], aH, b1H);
                    mma16816(c[nf + 1], aH, b1L);
                    mma16816(c[nf + 1], aL, b1H);
                }
            }
        }
        CP_WAIT0();
        __syncthreads();
    }

    const int gm = b * 16384 + h * 128 + w0 + wm + gid;
    #pragma unroll
    for (int nf = 0; nf < 8; ++nf) {
        int gn = wn + nf * 8 + tig * 2;
        float bx2 = __ldg(&bp[gn]), by2 = __ldg(&bp[gn + 1]);
        float2 v0 = { c[nf][0] + bx2, c[nf][1] + by2 };
        float2 v1 = { c[nf][2] + bx2, c[nf][3] + by2 };
        *(float2*)&out[(size_t)gm * FF + gn]       = v0;
        *(float2*)&out[(size_t)(gm + 8) * FF + gn] = v1;
    }
}

// ---------------------------------------------------------------------------
extern "C" void kernel_launch(void* const* d_in, const int* in_sizes, int n_in,
                              void* d_out, int out_size)
{
    const float* main_in = (const float*)d_in[0];
    const float* W1 = (const float*)d_in[2];
    const float* b1 = (const float*)d_in[3];
    const float* W2 = (const float*)d_in[4];
    const float* b2 = (const float*)d_in[5];
    const float* W3 = (const float*)d_in[6];
    const float* b3 = (const float*)d_in[7];
    const float* W4 = (const float*)d_in[8];
    const float* b4 = (const float*)d_in[9];
    const float* Wo = (const float*)d_in[10];
    const float* bo = (const float*)d_in[11];
    const float* Wp = (const float*)d_in[12];
    const float* bp = (const float*)d_in[13];
    float* out = (float*)d_out;

    cudaFuncSetAttribute(gemm2_fused5, cudaFuncAttributeMaxDynamicSharedMemorySize, SM_TOT);

    const int prep_elems = 4 * NG * 32 + 4 * NG + FF * CC + 4096 + 4096 + 32;
    prep_kernel<<<(prep_elems + 255) / 256, 256>>>(Wo, bo, Wp, W1, b1);
    mlp_kernel<<<1024, 256>>>(W2, b2, W3, b3, W4, b4);
    gemm1_kernel<<<dim3(128, 8), 256>>>();
    gemm2_fused5<<<1024, 256, SM_TOT>>>(main_in, bp, out);
}

// round 12
// speedup vs baseline: 1.3062x; 1.1327x over previous
#include <cuda_runtime.h>
#include <cuda_bf16.h>
#include <cuda_fp16.h>
#include <cstdint>
#include <math.h>

#define HT   128
#define CC   256
#define FF   128
#define BB   4
#define NU   32
#define NOUT 2304
#define NG   1024
#define PIF  3.14159265358979323846f

typedef __nv_bfloat16 bf16;

// ---------------- scratch globals ----------------
__device__ __align__(16) bf16   g_Wgh[4 * NG * 32];
__device__ __align__(16) bf16   g_Wgl[4 * NG * 32];
__device__ __align__(16) float  g_bg[4 * NG];
__device__ __align__(16) float  g_Hc[128 * 32];
__device__ __align__(16) float  g_Wc[128 * 32];
__device__ __align__(16) float  g_Cc[32];
__device__ __align__(16) bf16   g_x4h[(size_t)16384 * 32];
__device__ __align__(16) bf16   g_x4l[(size_t)16384 * 32];
__device__ __align__(16) __half g_WpT16[(size_t)FF * CC];    // [n][k] fp16
__device__ __align__(16) float  g_ker2[(size_t)16384 * NG];  // [p'][g*256+c]

__device__ __forceinline__ void split_bf(float v, bf16& hi, bf16& lo) {
    hi = __float2bfloat16(v);
    lo = __float2bfloat16(v - __bfloat162float(hi));
}
__device__ __forceinline__ void mma16816(float c[4], const uint32_t a[4], const uint32_t b[2]) {
    asm volatile(
        "mma.sync.aligned.m16n8k16.row.col.f32.bf16.bf16.f32 "
        "{%0,%1,%2,%3}, {%4,%5,%6,%7}, {%8,%9}, {%0,%1,%2,%3};"
        : "+f"(c[0]), "+f"(c[1]), "+f"(c[2]), "+f"(c[3])
        : "r"(a[0]), "r"(a[1]), "r"(a[2]), "r"(a[3]), "r"(b[0]), "r"(b[1]));
}
__device__ __forceinline__ void mma16816h(float c[4], const uint32_t a[4], const uint32_t b[2]) {
    asm volatile(
        "mma.sync.aligned.m16n8k16.row.col.f32.f16.f16.f32 "
        "{%0,%1,%2,%3}, {%4,%5,%6,%7}, {%8,%9}, {%0,%1,%2,%3};"
        : "+f"(c[0]), "+f"(c[1]), "+f"(c[2]), "+f"(c[3])
        : "r"(a[0]), "r"(a[1]), "r"(a[2]), "r"(a[3]), "r"(b[0]), "r"(b[1]));
}
__device__ __forceinline__ void ldsm_x4(uint32_t& r0, uint32_t& r1, uint32_t& r2, uint32_t& r3,
                                        uint32_t addr) {
    asm volatile("ldmatrix.sync.aligned.m8n8.x4.shared.b16 {%0,%1,%2,%3}, [%4];"
                 : "=r"(r0), "=r"(r1), "=r"(r2), "=r"(r3) : "r"(addr));
}
__device__ __forceinline__ int grp(int t, int par) { return (t == 0) ? 0 : (t == 2) ? 1 : (par ? 0 : 1); }

__device__ __forceinline__ void cp16(uint32_t dst, const void* src, int sz) {
    asm volatile("cp.async.cg.shared.global [%0], [%1], 16, %2;"
                 :: "r"(dst), "l"(src), "r"(sz));
}
#define CP_COMMIT() asm volatile("cp.async.commit_group;" ::: "memory")
#define CP_WAIT0()  asm volatile("cp.async.wait_group 0;" ::: "memory")

// ---------------------------------------------------------------------------
// prep
// ---------------------------------------------------------------------------
__global__ __launch_bounds__(256) void prep_kernel(
    const float* __restrict__ Wo, const float* __restrict__ bo,
    const float* __restrict__ Wp,
    const float* __restrict__ W1, const float* __restrict__ b1)
{
    int idx = blockIdx.x * 256 + threadIdx.x;
    if (idx < 4 * NG * 32) {
        int par = idx >> 15, rem = idx & 32767;
        int n = rem >> 5, k = rem & 31;
        int g = n >> 8, c = n & 255, gr = g >> 1, gc = g & 1;
        int ph = par >> 1, pw = par & 1;
        float s = 0.0f;
        #pragma unroll
        for (int tr = 0; tr < 3; ++tr)
            #pragma unroll
            for (int tc = 0; tc < 3; ++tc)
                if (grp(tr, ph) == gr && grp(tc, pw) == gc)
                    s += Wo[(size_t)k * NOUT + (tr * 3 + tc) * 256 + c];
        bf16 hi, lo; split_bf(s, hi, lo);
        g_Wgh[idx] = hi; g_Wgl[idx] = lo;
    } else if ((idx -= 4 * NG * 32) < 4 * NG) {
        int par = idx >> 10, n = idx & 1023;
        int g = n >> 8, c = n & 255, gr = g >> 1, gc = g & 1;
        int ph = par >> 1, pw = par & 1;
        float s = 0.0f;
        #pragma unroll
        for (int tr = 0; tr < 3; ++tr)
            #pragma unroll
            for (int tc = 0; tc < 3; ++tc)
                if (grp(tr, ph) == gr && grp(tc, pw) == gc)
                    s += bo[(tr * 3 + tc) * 256 + c];
        g_bg[idx] = s;
    } else if ((idx -= 4 * NG) < FF * CC) {
        int n = idx >> 8, k = idx & 255;
        g_WpT16[idx] = __float2half(Wp[(size_t)k * FF + n]);
    } else if ((idx -= FF * CC) < 4096) {
        int h = idx >> 5, j = idx & 31;
        float s = 0.0f;
        for (int i = 0; i < 25; ++i) {
            float f = 1.0f + (float)i * (1.0f / 24.0f);
            s += cosf(PIF * (2.0f * h * (1.0f / 127.0f) + 1.0f) * f) * W1[i * 32 + j];
        }
        g_Hc[idx] = s;
    } else if ((idx -= 4096) < 4096) {
        int w = idx >> 5, j = idx & 31;
        float s = 0.0f;
        for (int i = 0; i < 25; ++i) {
            float f = 1.0f + (float)i * (1.0f / 24.0f);
            s += cosf(PIF * (2.0f * w * (1.0f / 127.0f) + 1.0f) * f) * W1[(25 + i) * 32 + j];
        }
        g_Wc[idx] = s;
    } else if ((idx -= 4096) < 32) {
        int j = idx;
        float s = b1[j];
        for (int i = 0; i < 50; ++i) {
            float f = 1.0f + (float)(i % 25) * (1.0f / 24.0f);
            s += cosf(PIF * 5.0f * f) * W1[(50 + i) * 32 + j];
        }
        for (int i = 100; i < 118; ++i) s -= W1[i * 32 + j];
        g_Cc[j] = s;
    }
}

// ---------------------------------------------------------------------------
// mlp -> x4 hi/lo, parity-major p'
// ---------------------------------------------------------------------------
__global__ __launch_bounds__(256) void mlp_kernel(
    const float* __restrict__ W2, const float* __restrict__ b2,
    const float* __restrict__ W3, const float* __restrict__ b3,
    const float* __restrict__ W4, const float* __restrict__ b4)
{
    __shared__ float xa[16][32];
    __shared__ float xb[16][32];
    const int tid = threadIdx.x;
    const int pix0 = blockIdx.x * 16;

    for (int o = tid; o < 512; o += 256) {
        int p = o >> 5, j = o & 31;
        int pix = pix0 + p, h = pix >> 7, w = pix & 127;
        xa[p][j] = fmaxf(g_Hc[h * 32 + j] + g_Wc[w * 32 + j] + g_Cc[j], 0.0f);
    }
    __syncthreads();
    for (int o = tid; o < 512; o += 256) {
        int p = o >> 5, j = o & 31;
        float s = b2[j];
        #pragma unroll
        for (int k = 0; k < NU; ++k) s += xa[p][k] * W2[k * NU + j];
        xb[p][j] = fmaxf(s, 0.0f);
    }
    __syncthreads();
    for (int o = tid; o < 512; o += 256) {
        int p = o >> 5, j = o & 31;
        float s = b3[j];
        #pragma unroll
        for (int k = 0; k < NU; ++k) s += xb[p][k] * W3[k * NU + j];
        xa[p][j] = fmaxf(s, 0.0f);
    }
    __syncthreads();
    for (int o = tid; o < 512; o += 256) {
        int p = o >> 5, j = o & 31;
        float s = b4[j];
        #pragma unroll
        for (int k = 0; k < NU; ++k) s += xa[p][k] * W4[k * NU + j];
        float v = fmaxf(s, 0.0f);
        int pix = pix0 + p, h = pix >> 7, w = pix & 127;
        int pp = (((h & 1) << 1) | (w & 1)) * 4096 + (h >> 1) * 64 + (w >> 1);
        bf16 hi, lo; split_bf(v, hi, lo);
        size_t o2 = (size_t)pp * 32 + j;
        g_x4h[o2] = hi; g_x4l[o2] = lo;
    }
}

// ---------------------------------------------------------------------------
// gemm1: g_ker2 = x4 @ Wg[par] + bg[par]  (split-bf16, LDSM)
// ---------------------------------------------------------------------------
__global__ __launch_bounds__(256) void gemm1_kernel()
{
    __shared__ __align__(16) bf16 As[128 * 72];
    __shared__ __align__(16) bf16 Bs[128 * 72];

    const int tid = threadIdx.x;
    const int wid = tid >> 5, lane = tid & 31;
    const int gid = lane >> 2, tig = lane & 3;
    const int m0 = blockIdx.x * 128, n0g = blockIdx.y * 128;
    const int par = blockIdx.x >> 5;
    const int wm0 = (wid & 3) * 32, wn0 = (wid >> 2) * 64;

    const bf16* WgH = g_Wgh + (size_t)par * NG * 32;
    const bf16* WgL = g_Wgl + (size_t)par * NG * 32;

    for (int i = tid; i < 512; i += 256) {
        int r = i >> 2, q = (i & 3) * 8;
        *(uint4*)&As[r * 72 + q]      = *(const uint4*)&g_x4h[(size_t)(m0 + r) * 32 + q];
        *(uint4*)&As[r * 72 + 32 + q] = *(const uint4*)&g_x4l[(size_t)(m0 + r) * 32 + q];
        *(uint4*)&Bs[r * 72 + q]      = *(const uint4*)&WgH[(size_t)(n0g + r) * 32 + q];
        *(uint4*)&Bs[r * 72 + 32 + q] = *(const uint4*)&WgL[(size_t)(n0g + r) * 32 + q];
    }
    __syncthreads();

    const uint32_t smA = (uint32_t)__cvta_generic_to_shared(As);
    const uint32_t smB = (uint32_t)__cvta_generic_to_shared(Bs);
    const int aRow = (lane & 7) + ((lane >> 3) & 1) * 8;
    const int aCol = ((lane >> 4) & 1) * 8;
    const int bRow = (lane & 7) + ((lane >> 4) & 1) * 8;
    const int bCol = ((lane >> 3) & 1) * 8;

    float c[2][8][4];
    #pragma unroll
    for (int i = 0; i < 2; ++i)
        #pragma unroll
        for (int j = 0; j < 8; ++j)
            #pragma unroll
            for (int e = 0; e < 4; ++e) c[i][j][e] = 0.0f;

    #pragma unroll
    for (int ks = 0; ks < 2; ++ks) {
        const int kb = ks * 16;
        uint32_t aH[2][4], aL[2][4], bH[8][2], bL[8][2];
        #pragma unroll
        for (int mf = 0; mf < 2; ++mf) {
            uint32_t adr = smA + (uint32_t)((wm0 + mf * 16 + aRow) * 72 + kb + aCol) * 2;
            ldsm_x4(aH[mf][0], aH[mf][1], aH[mf][2], aH[mf][3], adr);
            ldsm_x4(aL[mf][0], aL[mf][1], aL[mf][2], aL[mf][3], adr + 64);
        }
        #pragma unroll
        for (int nf = 0; nf < 8; nf += 2) {
            uint32_t adr = smB + (uint32_t)((wn0 + nf * 8 + bRow) * 72 + kb + bCol) * 2;
            ldsm_x4(bH[nf][0], bH[nf][1], bH[nf + 1][0], bH[nf + 1][1], adr);
            ldsm_x4(bL[nf][0], bL[nf][1], bL[nf + 1][0], bL[nf + 1][1], adr + 64);
        }
        #pragma unroll
        for (int mf = 0; mf < 2; ++mf)
            #pragma unroll
            for (int nf = 0; nf < 8; ++nf) {
                mma16816(c[mf][nf], aH[mf], bH[nf]);
                mma16816(c[mf][nf], aH[mf], bL[nf]);
                mma16816(c[mf][nf], aL[mf], bH[nf]);
            }
    }

    const float* bgp = g_bg + par * NG;
    #pragma unroll
    for (int mf = 0; mf < 2; ++mf) {
        int gm = m0 + wm0 + mf * 16 + gid;
        #pragma unroll
        for (int nf = 0; nf < 8; ++nf) {
            int gn = n0g + wn0 + nf * 8 + tig * 2;
            float bx = __ldg(&bgp[gn]), by = __ldg(&bgp[gn + 1]);
            float2 v0 = { c[mf][nf][0] + bx, c[mf][nf][1] + by };
            float2 v1 = { c[mf][nf][2] + bx, c[mf][nf][3] + by };
            *(float2*)&g_ker2[(size_t)gm * NG + gn]       = v0;
            *(float2*)&g_ker2[(size_t)(gm + 8) * NG + gn] = v1;
        }
    }
}

// ---------------------------------------------------------------------------
// fused gemm2 v6b: single-fp16 MMA, fixed Bs double-buffer stride (10240 B).
// Half-row CTAs (64 m). smem: As 5.1KB | Bs 2x10.2KB | Xs 2x9.8KB = ~45KB.
// ---------------------------------------------------------------------------
#define SM_AS    0
#define SM_BS    5120
#define BS_BYTES 10240
#define SM_XS    (SM_BS + 2 * BS_BYTES)
#define SM_TOT   (SM_XS + 19584)
#define XS_FLTS  2448   // 2 rows * 34 cols * 36 stride
#define BSTR     40     // Bs/As row stride in halfs

__global__ __launch_bounds__(256, 3) void gemm2_fused6(
    const float* __restrict__ main_in,
    const float* __restrict__ bp, float* __restrict__ out)
{
    extern __shared__ __align__(16) uint8_t dsm[];
    __half* As = (__half*)(dsm + SM_AS);
    float*  Xs = (float*)(dsm + SM_XS);
    const uint32_t smb = (uint32_t)__cvta_generic_to_shared(dsm);

    const int tid = threadIdx.x;
    const int wid = tid >> 5, lane = tid & 31;
    const int gid = lane >> 2, tig = lane & 3;

    const int bx = blockIdx.x;
    const int whalf = bx & 1;
    const int b = (bx >> 1) & 3;
    const int h = bx >> 3;
    const int w0 = whalf * 64;
    const int c0 = whalf ? 31 : 0;

    const int wm = (wid & 3) * 16;
    const int wn = (wid >> 2) * 64;

    const int rA = (h - 1) >> 1, rB = (h + 1) >> 1;
    const bool vrA = h >= 1, vrB = h <= 126;

    const int awl = tid >> 2;
    const int w   = w0 + awl;
    const int ch0 = (tid & 3) * 8;
    const int par = ((h & 1) << 1) | (w & 1);
    const size_t pbase = ((size_t)par * 4096 + (h >> 1) * 64 + (w >> 1)) * NG;
    const int colA = ((w - 1) >> 1) - c0, colB = ((w + 1) >> 1) - c0;
    const bool vcA = w >= 1, vcB = w <= 126;

    const int aRow = (lane & 7) + ((lane >> 3) & 1) * 8;
    const int aCol = ((lane >> 4) & 1) * 8;
    const int bRow = (lane & 7) + ((lane >> 4) & 1) * 8;
    const int bCol = ((lane >> 3) & 1) * 8;

    float c[8][4];
    #pragma unroll
    for (int j = 0; j < 8; ++j)
        #pragma unroll
        for (int e = 0; e < 4; ++e) c[j][e] = 0.0f;

    auto stage = [&](int buf, int kc) {
        // Xs: 2 src rows x 34 cols x 32 ch (544 cp16)
        #pragma unroll
        for (int q = 0; q < 3; ++q) {
            int s = q * 256 + tid;
            if (s < 544) {
                int pos = s >> 3, qq = s & 7;
                int r = pos / 34, ci = pos - r * 34;
                int col = c0 + ci;
                bool ok = (r ? vrB : vrA) && (col < 64);
                int srow = r ? rB : rA; if (srow < 0) srow = 0;
                int scol = ok ? col : 0;
                const float* src = &main_in[(((size_t)b * 64 + srow) * 64 + scol) * CC + kc + qq * 4];
                uint32_t dst = smb + SM_XS + (uint32_t)(buf * XS_FLTS + pos * 36 + qq * 4) * 4;
                cp16(dst, src, ok ? 16 : 0);
            }
        }
        // Bs: Wp fp16 128n x 32k (512 cp16)
        #pragma unroll
        for (int q = 0; q < 2; ++q) {
            int s = q * 256 + tid;
            int n = s >> 2, part = s & 3;
            const __half* src = g_WpT16 + (size_t)n * CC + kc + part * 8;
            uint32_t dst = smb + SM_BS + (uint32_t)(buf * BS_BYTES + (n * BSTR + part * 8) * 2);
            cp16(dst, src, 16);
        }
        CP_COMMIT();
    };

    stage(0, 0);
    CP_WAIT0();
    __syncthreads();

    for (int chunk = 0; chunk < 8; ++chunk) {
        const int cur = chunk & 1;
        const int kc  = chunk * 32;

        // ---- build As (64w x 32ch fp16) ----
        {
            const float* Xb = Xs + cur * XS_FLTS;
            const float* kbp = g_ker2 + pbase + kc + ch0;
            float y[8];
            #pragma unroll
            for (int j = 0; j < 8; ++j) y[j] = 0.0f;
            #pragma unroll
            for (int g = 0; g < 4; ++g) {
                float4 k0 = *(const float4*)&kbp[g * 256];
                float4 k1 = *(const float4*)&kbp[g * 256 + 4];
                int  rr  = g >> 1;
                int  cr  = (g & 1) ? colB : colA;
                bool ok  = (g & 1) ? vcB : vcA;
                float4 s0 = make_float4(0.f, 0.f, 0.f, 0.f), s1 = s0;
                if (ok) {
                    s0 = *(const float4*)&Xb[(rr * 34 + cr) * 36 + ch0];
                    s1 = *(const float4*)&Xb[(rr * 34 + cr) * 36 + ch0 + 4];
                }
                y[0] += k0.x * s0.x; y[1] += k0.y * s0.y;
                y[2] += k0.z * s0.z; y[3] += k0.w * s0.w;
                y[4] += k1.x * s1.x; y[5] += k1.y * s1.y;
                y[6] += k1.z * s1.z; y[7] += k1.w * s1.w;
            }
            uint32_t hu[4];
            #pragma unroll
            for (int j2 = 0; j2 < 4; ++j2) {
                __half h0 = __float2half(y[j2 * 2]);
                __half h1 = __float2half(y[j2 * 2 + 1]);
                hu[j2] = (uint32_t)__half_as_ushort(h0) | ((uint32_t)__half_as_ushort(h1) << 16);
            }
            *(uint4*)&As[awl * BSTR + ch0] = make_uint4(hu[0], hu[1], hu[2], hu[3]);
        }
        __syncthreads();

        // ---- stage next (async) + MMA (1 combo fp16) ----
        if (chunk < 7) stage(cur ^ 1, kc + 32);
        {
            const uint32_t smAa = smb + SM_AS;
            const uint32_t smBb = smb + SM_BS + (uint32_t)(cur * BS_BYTES);
            #pragma unroll
            for (int ks2 = 0; ks2 < 2; ++ks2) {
                const int kb = ks2 * 16;
                uint32_t a[4];
                {
                    uint32_t adr = smAa + (uint32_t)((wm + aRow) * BSTR + kb + aCol) * 2;
                    ldsm_x4(a[0], a[1], a[2], a[3], adr);
                }
                #pragma unroll
                for (int nf = 0; nf < 8; nf += 2) {
                    uint32_t b0[2], b1[2];
                    uint32_t adr = smBb + (uint32_t)((wn + nf * 8 + bRow) * BSTR + kb + bCol) * 2;
                    ldsm_x4(b0[0], b0[1], b1[0], b1[1], adr);
                    mma16816h(c[nf],     a, b0);
                    mma16816h(c[nf + 1], a, b1);
                }
            }
        }
        CP_WAIT0();
        __syncthreads();
    }

    const int gm = b * 16384 + h * 128 + w0 + wm + gid;
    #pragma unroll
    for (int nf = 0; nf < 8; ++nf) {
        int gn = wn + nf * 8 + tig * 2;
        float bx2 = __ldg(&bp[gn]), by2 = __ldg(&bp[gn + 1]);
        float2 v0 = { c[nf][0] + bx2, c[nf][1] + by2 };
        float2 v1 = { c[nf][2] + bx2, c[nf][3] + by2 };
        *(float2*)&out[(size_t)gm * FF + gn]       = v0;
        *(float2*)&out[(size_t)(gm + 8) * FF + gn] = v1;
    }
}

// ---------------------------------------------------------------------------
extern "C" void kernel_launch(void* const* d_in, const int* in_sizes, int n_in,
                              void* d_out, int out_size)
{
    const float* main_in = (const float*)d_in[0];
    const float* W1 = (const float*)d_in[2];
    const float* b1 = (const float*)d_in[3];
    const float* W2 = (const float*)d_in[4];
    const float* b2 = (const float*)d_in[5];
    const float* W3 = (const float*)d_in[6];
    const float* b3 = (const float*)d_in[7];
    const float* W4 = (const float*)d_in[8];
    const float* b4 = (const float*)d_in[9];
    const float* Wo = (const float*)d_in[10];
    const float* bo = (const float*)d_in[11];
    const float* Wp = (const float*)d_in[12];
    const float* bp = (const float*)d_in[13];
    float* out = (float*)d_out;

    cudaFuncSetAttribute(gemm2_fused6, cudaFuncAttributeMaxDynamicSharedMemorySize, SM_TOT);

    const int prep_elems = 4 * NG * 32 + 4 * NG + FF * CC + 4096 + 4096 + 32;
    prep_kernel<<<(prep_elems + 255) / 256, 256>>>(Wo, bo, Wp, W1, b1);
    mlp_kernel<<<1024, 256>>>(W2, b2, W3, b3, W4, b4);
    gemm1_kernel<<<dim3(128, 8), 256>>>();
    gemm2_fused6<<<1024, 256, SM_TOT>>>(main_in, bp, out);
}

// round 13
// speedup vs baseline: 1.6121x; 1.2342x over previous
#include <cuda_runtime.h>
#include <cuda_bf16.h>
#include <cuda_fp16.h>
#include <cstdint>
#include <math.h>

#define HT   128
#define CC   256
#define FF   128
#define BB   4
#define NU   32
#define NOUT 2304
#define NG   1024
#define PIF  3.14159265358979323846f

typedef __nv_bfloat16 bf16;

// ---------------- scratch globals ----------------
__device__ __align__(16) bf16   g_Wgh[4 * NG * 32];
__device__ __align__(16) bf16   g_Wgl[4 * NG * 32];
__device__ __align__(16) float  g_bg[4 * NG];
__device__ __align__(16) float  g_Hc[128 * 32];
__device__ __align__(16) float  g_Wc[128 * 32];
__device__ __align__(16) float  g_Cc[32];
__device__ __align__(16) bf16   g_x4h[(size_t)16384 * 32];
__device__ __align__(16) bf16   g_x4l[(size_t)16384 * 32];
__device__ __align__(16) __half g_WpT16[(size_t)FF * CC];     // [n][k] fp16
__device__ __align__(16) __half g_ker16[(size_t)16384 * NG];  // [p'][g*256+c] fp16 (33.5MB)

__device__ __forceinline__ void split_bf(float v, bf16& hi, bf16& lo) {
    hi = __float2bfloat16(v);
    lo = __float2bfloat16(v - __bfloat162float(hi));
}
__device__ __forceinline__ void mma16816(float c[4], const uint32_t a[4], const uint32_t b[2]) {
    asm volatile(
        "mma.sync.aligned.m16n8k16.row.col.f32.bf16.bf16.f32 "
        "{%0,%1,%2,%3}, {%4,%5,%6,%7}, {%8,%9}, {%0,%1,%2,%3};"
        : "+f"(c[0]), "+f"(c[1]), "+f"(c[2]), "+f"(c[3])
        : "r"(a[0]), "r"(a[1]), "r"(a[2]), "r"(a[3]), "r"(b[0]), "r"(b[1]));
}
__device__ __forceinline__ void mma16816h(float c[4], const uint32_t a[4], const uint32_t b[2]) {
    asm volatile(
        "mma.sync.aligned.m16n8k16.row.col.f32.f16.f16.f32 "
        "{%0,%1,%2,%3}, {%4,%5,%6,%7}, {%8,%9}, {%0,%1,%2,%3};"
        : "+f"(c[0]), "+f"(c[1]), "+f"(c[2]), "+f"(c[3])
        : "r"(a[0]), "r"(a[1]), "r"(a[2]), "r"(a[3]), "r"(b[0]), "r"(b[1]));
}
__device__ __forceinline__ void ldsm_x4(uint32_t& r0, uint32_t& r1, uint32_t& r2, uint32_t& r3,
                                        uint32_t addr) {
    asm volatile("ldmatrix.sync.aligned.m8n8.x4.shared.b16 {%0,%1,%2,%3}, [%4];"
                 : "=r"(r0), "=r"(r1), "=r"(r2), "=r"(r3) : "r"(addr));
}
__device__ __forceinline__ int grp(int t, int par) { return (t == 0) ? 0 : (t == 2) ? 1 : (par ? 0 : 1); }

__device__ __forceinline__ void cp16(uint32_t dst, const void* src, int sz) {
    asm volatile("cp.async.cg.shared.global [%0], [%1], 16, %2;"
                 :: "r"(dst), "l"(src), "r"(sz));
}
#define CP_COMMIT() asm volatile("cp.async.commit_group;" ::: "memory")
#define CP_WAIT0()  asm volatile("cp.async.wait_group 0;" ::: "memory")

// ---------------------------------------------------------------------------
// prep
// ---------------------------------------------------------------------------
__global__ __launch_bounds__(256) void prep_kernel(
    const float* __restrict__ Wo, const float* __restrict__ bo,
    const float* __restrict__ Wp,
    const float* __restrict__ W1, const float* __restrict__ b1)
{
    int idx = blockIdx.x * 256 + threadIdx.x;
    if (idx < 4 * NG * 32) {
        int par = idx >> 15, rem = idx & 32767;
        int n = rem >> 5, k = rem & 31;
        int g = n >> 8, c = n & 255, gr = g >> 1, gc = g & 1;
        int ph = par >> 1, pw = par & 1;
        float s = 0.0f;
        #pragma unroll
        for (int tr = 0; tr < 3; ++tr)
            #pragma unroll
            for (int tc = 0; tc < 3; ++tc)
                if (grp(tr, ph) == gr && grp(tc, pw) == gc)
                    s += Wo[(size_t)k * NOUT + (tr * 3 + tc) * 256 + c];
        bf16 hi, lo; split_bf(s, hi, lo);
        g_Wgh[idx] = hi; g_Wgl[idx] = lo;
    } else if ((idx -= 4 * NG * 32) < 4 * NG) {
        int par = idx >> 10, n = idx & 1023;
        int g = n >> 8, c = n & 255, gr = g >> 1, gc = g & 1;
        int ph = par >> 1, pw = par & 1;
        float s = 0.0f;
        #pragma unroll
        for (int tr = 0; tr < 3; ++tr)
            #pragma unroll
            for (int tc = 0; tc < 3; ++tc)
                if (grp(tr, ph) == gr && grp(tc, pw) == gc)
                    s += bo[(tr * 3 + tc) * 256 + c];
        g_bg[idx] = s;
    } else if ((idx -= 4 * NG) < FF * CC) {
        int n = idx >> 8, k = idx & 255;
        g_WpT16[idx] = __float2half(Wp[(size_t)k * FF + n]);
    } else if ((idx -= FF * CC) < 4096) {
        int h = idx >> 5, j = idx & 31;
        float s = 0.0f;
        for (int i = 0; i < 25; ++i) {
            float f = 1.0f + (float)i * (1.0f / 24.0f);
            s += cosf(PIF * (2.0f * h * (1.0f / 127.0f) + 1.0f) * f) * W1[i * 32 + j];
        }
        g_Hc[idx] = s;
    } else if ((idx -= 4096) < 4096) {
        int w = idx >> 5, j = idx & 31;
        float s = 0.0f;
        for (int i = 0; i < 25; ++i) {
            float f = 1.0f + (float)i * (1.0f / 24.0f);
            s += cosf(PIF * (2.0f * w * (1.0f / 127.0f) + 1.0f) * f) * W1[(25 + i) * 32 + j];
        }
        g_Wc[idx] = s;
    } else if ((idx -= 4096) < 32) {
        int j = idx;
        float s = b1[j];
        for (int i = 0; i < 50; ++i) {
            float f = 1.0f + (float)(i % 25) * (1.0f / 24.0f);
            s += cosf(PIF * 5.0f * f) * W1[(50 + i) * 32 + j];
        }
        for (int i = 100; i < 118; ++i) s -= W1[i * 32 + j];
        g_Cc[j] = s;
    }
}

// ---------------------------------------------------------------------------
// mlp -> x4 hi/lo, parity-major p'
// ---------------------------------------------------------------------------
__global__ __launch_bounds__(256) void mlp_kernel(
    const float* __restrict__ W2, const float* __restrict__ b2,
    const float* __restrict__ W3, const float* __restrict__ b3,
    const float* __restrict__ W4, const float* __restrict__ b4)
{
    __shared__ float xa[16][32];
    __shared__ float xb[16][32];
    const int tid = threadIdx.x;
    const int pix0 = blockIdx.x * 16;

    for (int o = tid; o < 512; o += 256) {
        int p = o >> 5, j = o & 31;
        int pix = pix0 + p, h = pix >> 7, w = pix & 127;
        xa[p][j] = fmaxf(g_Hc[h * 32 + j] + g_Wc[w * 32 + j] + g_Cc[j], 0.0f);
    }
    __syncthreads();
    for (int o = tid; o < 512; o += 256) {
        int p = o >> 5, j = o & 31;
        float s = b2[j];
        #pragma unroll
        for (int k = 0; k < NU; ++k) s += xa[p][k] * W2[k * NU + j];
        xb[p][j] = fmaxf(s, 0.0f);
    }
    __syncthreads();
    for (int o = tid; o < 512; o += 256) {
        int p = o >> 5, j = o & 31;
        float s = b3[j];
        #pragma unroll
        for (int k = 0; k < NU; ++k) s += xb[p][k] * W3[k * NU + j];
        xa[p][j] = fmaxf(s, 0.0f);
    }
    __syncthreads();
    for (int o = tid; o < 512; o += 256) {
        int p = o >> 5, j = o & 31;
        float s = b4[j];
        #pragma unroll
        for (int k = 0; k < NU; ++k) s += xa[p][k] * W4[k * NU + j];
        float v = fmaxf(s, 0.0f);
        int pix = pix0 + p, h = pix >> 7, w = pix & 127;
        int pp = (((h & 1) << 1) | (w & 1)) * 4096 + (h >> 1) * 64 + (w >> 1);
        bf16 hi, lo; split_bf(v, hi, lo);
        size_t o2 = (size_t)pp * 32 + j;
        g_x4h[o2] = hi; g_x4l[o2] = lo;
    }
}

// ---------------------------------------------------------------------------
// gemm1: g_ker16 = fp16(x4 @ Wg[par] + bg[par])  (split-bf16 MMA, fp16 store)
// ---------------------------------------------------------------------------
__global__ __launch_bounds__(256) void gemm1_kernel()
{
    __shared__ __align__(16) bf16 As[128 * 72];
    __shared__ __align__(16) bf16 Bs[128 * 72];

    const int tid = threadIdx.x;
    const int wid = tid >> 5, lane = tid & 31;
    const int gid = lane >> 2, tig = lane & 3;
    const int m0 = blockIdx.x * 128, n0g = blockIdx.y * 128;
    const int par = blockIdx.x >> 5;
    const int wm0 = (wid & 3) * 32, wn0 = (wid >> 2) * 64;

    const bf16* WgH = g_Wgh + (size_t)par * NG * 32;
    const bf16* WgL = g_Wgl + (size_t)par * NG * 32;

    for (int i = tid; i < 512; i += 256) {
        int r = i >> 2, q = (i & 3) * 8;
        *(uint4*)&As[r * 72 + q]      = *(const uint4*)&g_x4h[(size_t)(m0 + r) * 32 + q];
        *(uint4*)&As[r * 72 + 32 + q] = *(const uint4*)&g_x4l[(size_t)(m0 + r) * 32 + q];
        *(uint4*)&Bs[r * 72 + q]      = *(const uint4*)&WgH[(size_t)(n0g + r) * 32 + q];
        *(uint4*)&Bs[r * 72 + 32 + q] = *(const uint4*)&WgL[(size_t)(n0g + r) * 32 + q];
    }
    __syncthreads();

    const uint32_t smA = (uint32_t)__cvta_generic_to_shared(As);
    const uint32_t smB = (uint32_t)__cvta_generic_to_shared(Bs);
    const int aRow = (lane & 7) + ((lane >> 3) & 1) * 8;
    const int aCol = ((lane >> 4) & 1) * 8;
    const int bRow = (lane & 7) + ((lane >> 4) & 1) * 8;
    const int bCol = ((lane >> 3) & 1) * 8;

    float c[2][8][4];
    #pragma unroll
    for (int i = 0; i < 2; ++i)
        #pragma unroll
        for (int j = 0; j < 8; ++j)
            #pragma unroll
            for (int e = 0; e < 4; ++e) c[i][j][e] = 0.0f;

    #pragma unroll
    for (int ks = 0; ks < 2; ++ks) {
        const int kb = ks * 16;
        uint32_t aH[2][4], aL[2][4], bH[8][2], bL[8][2];
        #pragma unroll
        for (int mf = 0; mf < 2; ++mf) {
            uint32_t adr = smA + (uint32_t)((wm0 + mf * 16 + aRow) * 72 + kb + aCol) * 2;
            ldsm_x4(aH[mf][0], aH[mf][1], aH[mf][2], aH[mf][3], adr);
            ldsm_x4(aL[mf][0], aL[mf][1], aL[mf][2], aL[mf][3], adr + 64);
        }
        #pragma unroll
        for (int nf = 0; nf < 8; nf += 2) {
            uint32_t adr = smB + (uint32_t)((wn0 + nf * 8 + bRow) * 72 + kb + bCol) * 2;
            ldsm_x4(bH[nf][0], bH[nf][1], bH[nf + 1][0], bH[nf + 1][1], adr);
            ldsm_x4(bL[nf][0], bL[nf][1], bL[nf + 1][0], bL[nf + 1][1], adr + 64);
        }
        #pragma unroll
        for (int mf = 0; mf < 2; ++mf)
            #pragma unroll
            for (int nf = 0; nf < 8; ++nf) {
                mma16816(c[mf][nf], aH[mf], bH[nf]);
                mma16816(c[mf][nf], aH[mf], bL[nf]);
                mma16816(c[mf][nf], aL[mf], bH[nf]);
            }
    }

    const float* bgp = g_bg + par * NG;
    #pragma unroll
    for (int mf = 0; mf < 2; ++mf) {
        int gm = m0 + wm0 + mf * 16 + gid;
        #pragma unroll
        for (int nf = 0; nf < 8; ++nf) {
            int gn = n0g + wn0 + nf * 8 + tig * 2;
            float bx = __ldg(&bgp[gn]), by = __ldg(&bgp[gn + 1]);
            __half2 p0 = __floats2half2_rn(c[mf][nf][0] + bx, c[mf][nf][1] + by);
            __half2 p1 = __floats2half2_rn(c[mf][nf][2] + bx, c[mf][nf][3] + by);
            *(__half2*)&g_ker16[(size_t)gm * NG + gn]       = p0;
            *(__half2*)&g_ker16[(size_t)(gm + 8) * NG + gn] = p1;
        }
    }
}

// ---------------------------------------------------------------------------
// fused gemm2 v7: fp16 ker2 + register k-prefetch in MMA phase.
// Half-row CTAs (64 m). smem: As 5.1KB | Bs 2x10.2KB | Xs 2x9.8KB = ~45KB.
// ---------------------------------------------------------------------------
#define SM_AS    0
#define SM_BS    5120
#define BS_BYTES 10240
#define SM_XS    (SM_BS + 2 * BS_BYTES)
#define SM_TOT   (SM_XS + 19584)
#define XS_FLTS  2448
#define BSTR     40

__global__ __launch_bounds__(256, 3) void gemm2_fused7(
    const float* __restrict__ main_in,
    const float* __restrict__ bp, float* __restrict__ out)
{
    extern __shared__ __align__(16) uint8_t dsm[];
    __half* As = (__half*)(dsm + SM_AS);
    float*  Xs = (float*)(dsm + SM_XS);
    const uint32_t smb = (uint32_t)__cvta_generic_to_shared(dsm);

    const int tid = threadIdx.x;
    const int wid = tid >> 5, lane = tid & 31;
    const int gid = lane >> 2, tig = lane & 3;

    const int bx = blockIdx.x;
    const int whalf = bx & 1;
    const int b = (bx >> 1) & 3;
    const int h = bx >> 3;
    const int w0 = whalf * 64;
    const int c0 = whalf ? 31 : 0;

    const int wm = (wid & 3) * 16;
    const int wn = (wid >> 2) * 64;

    const int rA = (h - 1) >> 1, rB = (h + 1) >> 1;
    const bool vrA = h >= 1, vrB = h <= 126;

    const int awl = tid >> 2;
    const int w   = w0 + awl;
    const int ch0 = (tid & 3) * 8;
    const int par = ((h & 1) << 1) | (w & 1);
    const __half* kbase = g_ker16 + ((size_t)par * 4096 + (h >> 1) * 64 + (w >> 1)) * NG + ch0;
    const int colA = ((w - 1) >> 1) - c0, colB = ((w + 1) >> 1) - c0;
    const bool vcA = w >= 1, vcB = w <= 126;

    const int aRow = (lane & 7) + ((lane >> 3) & 1) * 8;
    const int aCol = ((lane >> 4) & 1) * 8;
    const int bRow = (lane & 7) + ((lane >> 4) & 1) * 8;
    const int bCol = ((lane >> 3) & 1) * 8;

    float c[8][4];
    #pragma unroll
    for (int j = 0; j < 8; ++j)
        #pragma unroll
        for (int e = 0; e < 4; ++e) c[j][e] = 0.0f;

    auto stage = [&](int buf, int kc) {
        #pragma unroll
        for (int q = 0; q < 3; ++q) {
            int s = q * 256 + tid;
            if (s < 544) {
                int pos = s >> 3, qq = s & 7;
                int r = pos / 34, ci = pos - r * 34;
                int col = c0 + ci;
                bool ok = (r ? vrB : vrA) && (col < 64);
                int srow = r ? rB : rA; if (srow < 0) srow = 0;
                int scol = ok ? col : 0;
                const float* src = &main_in[(((size_t)b * 64 + srow) * 64 + scol) * CC + kc + qq * 4];
                uint32_t dst = smb + SM_XS + (uint32_t)(buf * XS_FLTS + pos * 36 + qq * 4) * 4;
                cp16(dst, src, ok ? 16 : 0);
            }
        }
        #pragma unroll
        for (int q = 0; q < 2; ++q) {
            int s = q * 256 + tid;
            int n = s >> 2, part = s & 3;
            const __half* src = g_WpT16 + (size_t)n * CC + kc + part * 8;
            uint32_t dst = smb + SM_BS + (uint32_t)(buf * BS_BYTES + (n * BSTR + part * 8) * 2);
            cp16(dst, src, 16);
        }
        CP_COMMIT();
    };

    // k prefetch registers: 4 groups x 8 halves
    uint4 kq[4];
    #pragma unroll
    for (int g = 0; g < 4; ++g) kq[g] = *(const uint4*)&kbase[g * 256];

    stage(0, 0);
    CP_WAIT0();
    __syncthreads();

    for (int chunk = 0; chunk < 8; ++chunk) {
        const int cur = chunk & 1;
        const int kc  = chunk * 32;

        // ---- build As (64w x 32ch fp16) from kq (regs) + Xs[cur] ----
        {
            const float* Xb = Xs + cur * XS_FLTS;
            float y[8];
            #pragma unroll
            for (int j = 0; j < 8; ++j) y[j] = 0.0f;
            #pragma unroll
            for (int g = 0; g < 4; ++g) {
                int  rr  = g >> 1;
                int  cr  = (g & 1) ? colB : colA;
                bool ok  = (g & 1) ? vcB : vcA;
                float4 s0 = make_float4(0.f, 0.f, 0.f, 0.f), s1 = s0;
                if (ok) {
                    s0 = *(const float4*)&Xb[(rr * 34 + cr) * 36 + ch0];
                    s1 = *(const float4*)&Xb[(rr * 34 + cr) * 36 + ch0 + 4];
                }
                const __half2* kh = (const __half2*)&kq[g];
                float2 k01 = __half22float2(kh[0]);
                float2 k23 = __half22float2(kh[1]);
                float2 k45 = __half22float2(kh[2]);
                float2 k67 = __half22float2(kh[3]);
                y[0] += k01.x * s0.x; y[1] += k01.y * s0.y;
                y[2] += k23.x * s0.z; y[3] += k23.y * s0.w;
                y[4] += k45.x * s1.x; y[5] += k45.y * s1.y;
                y[6] += k67.x * s1.z; y[7] += k67.y * s1.w;
            }
            uint32_t hu[4];
            #pragma unroll
            for (int j2 = 0; j2 < 4; ++j2) {
                __half h0 = __float2half(y[j2 * 2]);
                __half h1 = __float2half(y[j2 * 2 + 1]);
                hu[j2] = (uint32_t)__half_as_ushort(h0) | ((uint32_t)__half_as_ushort(h1) << 16);
            }
            *(uint4*)&As[awl * BSTR + ch0] = make_uint4(hu[0], hu[1], hu[2], hu[3]);
        }
        __syncthreads();

        // ---- stage next + k prefetch (regs) + MMA ----
        if (chunk < 7) {
            stage(cur ^ 1, kc + 32);
            const __half* kbp = kbase + kc + 32;
            #pragma unroll
            for (int g = 0; g < 4; ++g) kq[g] = *(const uint4*)&kbp[g * 256];
        }
        {
            const uint32_t smAa = smb + SM_AS;
            const uint32_t smBb = smb + SM_BS + (uint32_t)(cur * BS_BYTES);
            #pragma unroll
            for (int ks2 = 0; ks2 < 2; ++ks2) {
                const int kb = ks2 * 16;
                uint32_t a[4];
                {
                    uint32_t adr = smAa + (uint32_t)((wm + aRow) * BSTR + kb + aCol) * 2;
                    ldsm_x4(a[0], a[1], a[2], a[3], adr);
                }
                #pragma unroll
                for (int nf = 0; nf < 8; nf += 2) {
                    uint32_t b0[2], b1[2];
                    uint32_t adr = smBb + (uint32_t)((wn + nf * 8 + bRow) * BSTR + kb + bCol) * 2;
                    ldsm_x4(b0[0], b0[1], b1[0], b1[1], adr);
                    mma16816h(c[nf],     a, b0);
                    mma16816h(c[nf + 1], a, b1);
                }
            }
        }
        CP_WAIT0();
        __syncthreads();
    }

    const int gm = b * 16384 + h * 128 + w0 + wm + gid;
    #pragma unroll
    for (int nf = 0; nf < 8; ++nf) {
        int gn = wn + nf * 8 + tig * 2;
        float bx2 = __ldg(&bp[gn]), by2 = __ldg(&bp[gn + 1]);
        float2 v0 = { c[nf][0] + bx2, c[nf][1] + by2 };
        float2 v1 = { c[nf][2] + bx2, c[nf][3] + by2 };
        *(float2*)&out[(size_t)gm * FF + gn]       = v0;
        *(float2*)&out[(size_t)(gm + 8) * FF + gn] = v1;
    }
}

// ---------------------------------------------------------------------------
extern "C" void kernel_launch(void* const* d_in, const int* in_sizes, int n_in,
                              void* d_out, int out_size)
{
    const float* main_in = (const float*)d_in[0];
    const float* W1 = (const float*)d_in[2];
    const float* b1 = (const float*)d_in[3];
    const float* W2 = (const float*)d_in[4];
    const float* b2 = (const float*)d_in[5];
    const float* W3 = (const float*)d_in[6];
    const float* b3 = (const float*)d_in[7];
    const float* W4 = (const float*)d_in[8];
    const float* b4 = (const float*)d_in[9];
    const float* Wo = (const float*)d_in[10];
    const float* bo = (const float*)d_in[11];
    const float* Wp = (const float*)d_in[12];
    const float* bp = (const float*)d_in[13];
    float* out = (float*)d_out;

    cudaFuncSetAttribute(gemm2_fused7, cudaFuncAttributeMaxDynamicSharedMemorySize, SM_TOT);

    const int prep_elems = 4 * NG * 32 + 4 * NG + FF * CC + 4096 + 4096 + 32;
    prep_kernel<<<(prep_elems + 255) / 256, 256>>>(Wo, bo, Wp, W1, b1);
    mlp_kernel<<<1024, 256>>>(W2, b2, W3, b3, W4, b4);
    gemm1_kernel<<<dim3(128, 8), 256>>>();
    gemm2_fused7<<<1024, 256, SM_TOT>>>(main_in, bp, out);
}